// round 7
// baseline (speedup 1.0000x reference)
#include <cuda_runtime.h>
#include <cuda_bf16.h>
#include <cstdint>

#define HIDDEN 1024
#define HEADS 16
#define HD 64
#define NVID 2048
#define NACT 16
#define NTOT 2064
#define BSZ 2
#define BH (BSZ*HEADS)
// q pre-scale: ATT_SCALE * log2(e), so softmax uses exp2
#define QSC 0.18033688011112042f

#define WSZ 1048576LL
#define OFF_VIDEO 0LL
#define OFF_ACTION 4194304LL
#define OFF_W 4227072LL
#define OFF_CTX (OFF_W + 8LL * WSZ)
#define BF_TOTAL (OFF_CTX + 4227072LL)

// ---------------- scratch (device globals; no allocation allowed) ----------------
__device__ unsigned short g_bh[BF_TOTAL];    // bf16 hi: inputs, weights, ctx
__device__ unsigned short g_bl[BF_TOTAL];    // bf16 lo
__device__ unsigned short g_qh[BH * NTOT * HD], g_ql[BH * NTOT * HD];
__device__ unsigned short g_kh[BH * NTOT * HD], g_kl[BH * NTOT * HD];
__device__ unsigned short g_vh[BH * NTOT * HD], g_vl[BH * NTOT * HD];

// ---------------- helpers ----------------
__device__ __forceinline__ void cpa16z(uint32_t dst, const void* src, int bytes) {
    asm volatile("cp.async.cg.shared.global [%0], [%1], 16, %2;"
                 :: "r"(dst), "l"(src), "r"(bytes) : "memory");
}
__device__ __forceinline__ void cp_commit() {
    asm volatile("cp.async.commit_group;" ::: "memory");
}
__device__ __forceinline__ uint32_t smem_u32(const void* p) {
    return (uint32_t)__cvta_generic_to_shared(p);
}
__device__ __forceinline__ void ldm4(uint32_t* r, uint32_t addr) {
    asm volatile("ldmatrix.sync.aligned.m8n8.x4.shared.b16 {%0,%1,%2,%3}, [%4];"
                 : "=r"(r[0]), "=r"(r[1]), "=r"(r[2]), "=r"(r[3]) : "r"(addr));
}
__device__ __forceinline__ void ldm4t(uint32_t* r, uint32_t addr) {
    asm volatile("ldmatrix.sync.aligned.m8n8.x4.trans.shared.b16 {%0,%1,%2,%3}, [%4];"
                 : "=r"(r[0]), "=r"(r[1]), "=r"(r[2]), "=r"(r[3]) : "r"(addr));
}
__device__ __forceinline__ void mma16816(float* c, const uint32_t* a,
                                         uint32_t b0, uint32_t b1) {
    asm volatile("mma.sync.aligned.m16n8k16.row.col.f32.bf16.bf16.f32 "
                 "{%0,%1,%2,%3}, {%4,%5,%6,%7}, {%8,%9}, {%0,%1,%2,%3};"
                 : "+f"(c[0]), "+f"(c[1]), "+f"(c[2]), "+f"(c[3])
                 : "r"(a[0]), "r"(a[1]), "r"(a[2]), "r"(a[3]), "r"(b0), "r"(b1));
}
__device__ __forceinline__ void bsplit(float x, unsigned short& h, unsigned short& l) {
    __nv_bfloat16 hb = __float2bfloat16_rn(x);
    h = __bfloat16_as_ushort(hb);
    l = __bfloat16_as_ushort(__float2bfloat16_rn(x - __bfloat162float(hb)));
}
__device__ __forceinline__ uint32_t pkbf(float lo, float hi) {
    uint32_t r;
    asm("cvt.rn.bf16x2.f32 %0, %1, %2;" : "=r"(r) : "f"(hi), "f"(lo));
    return r;
}
__device__ __forceinline__ float ex2f(float x) {
    float y; asm("ex2.approx.ftz.f32 %0, %1;" : "=f"(y) : "f"(x)); return y;
}

// ---------------- fp32 -> bf16 hi/lo split (inputs + weights) ----------------
__global__ void cvt_all(const float* v, const float* a,
                        const float* w0, const float* w1, const float* w2,
                        const float* w3, const float* w4, const float* w5,
                        const float* w6, const float* w7)
{
    const float* srcs[10] = { v, a, w0, w1, w2, w3, w4, w5, w6, w7 };
    const long long offs[10] = { OFF_VIDEO, OFF_ACTION,
        OFF_W + 0 * WSZ, OFF_W + 1 * WSZ, OFF_W + 2 * WSZ, OFF_W + 3 * WSZ,
        OFF_W + 4 * WSZ, OFF_W + 5 * WSZ, OFF_W + 6 * WSZ, OFF_W + 7 * WSZ };
    const int cnts[10] = { 4194304, 32768, 1048576, 1048576, 1048576, 1048576,
                           1048576, 1048576, 1048576, 1048576 };
    const int z = blockIdx.y;
    const float4* src = (const float4*)srcs[z];
    ushort4* hi = (ushort4*)(g_bh + offs[z]);
    ushort4* lo = (ushort4*)(g_bl + offs[z]);
    const int n4 = cnts[z] >> 2;
    for (int i = blockIdx.x * blockDim.x + threadIdx.x; i < n4;
         i += gridDim.x * blockDim.x) {
        const float4 x = src[i];
        ushort4 h, l;
        bsplit(x.x, h.x, l.x); bsplit(x.y, h.y, l.y);
        bsplit(x.z, h.z, l.z); bsplit(x.w, h.w, l.w);
        hi[i] = h; lo[i] = l;
    }
}

// ================= mma.sync bf16x3 GEMM (projections) =================
#define GT_TILE 16384
#define GT_BUF  (4 * GT_TILE)
#define GT_SMEM (2 * GT_BUF)

__device__ __forceinline__ void gstage(const unsigned short* Ah, const unsigned short* Al,
                                       int M, int rowTile,
                                       const unsigned short* Wh, const unsigned short* Wl,
                                       int colTile, int k0, uint32_t bufb, int tid)
{
#pragma unroll
    for (int i = 0; i < 16; i++) {
        const int tile = i >> 2;
        const int t = ((i & 3) << 8) + tid;
        const int row = t >> 3, c = t & 7;
        const uint32_t dst = bufb + tile * GT_TILE + (row << 7) + ((c ^ (row & 7)) << 4);
        if (tile == 0 || tile == 1) {
            const int m = rowTile + row;
            const int mm = (m < M) ? m : 0;
            const unsigned short* s = (tile == 0 ? Ah : Al) + (long long)mm * 1024 + k0 + c * 8;
            cpa16z(dst, s, (m < M) ? 16 : 0);
        } else {
            const unsigned short* s = (tile == 2 ? Wh : Wl) +
                                      (long long)(colTile + row) * 1024 + k0 + c * 8;
            cpa16z(dst, s, 16);
        }
    }
}

// MODE 0: fp32 out[m*1024+n];  MODE 1: video qkv split+rope;  MODE 2: action qkv split
template <int MODE>
__device__ __forceinline__ void gemm_body(const unsigned short* Ah, const unsigned short* Al,
                                          int M, int rowTile,
                                          const unsigned short* Wh, const unsigned short* Wl,
                                          int colTile, const float* bias,
                                          float* __restrict__ outf,
                                          unsigned short* __restrict__ oh,
                                          unsigned short* __restrict__ ol, int rk)
{
    extern __shared__ char dsmem[];
    const uint32_t sbase = smem_u32(dsmem);
    const int tid = threadIdx.x;
    const int lane = tid & 31, wid = tid >> 5;
    const int warp_m = wid >> 2, warp_n = wid & 3;

    float acc[4][4][4];
#pragma unroll
    for (int a = 0; a < 4; a++)
#pragma unroll
        for (int b = 0; b < 4; b++)
#pragma unroll
            for (int c = 0; c < 4; c++) acc[a][b][c] = 0.f;

    int rA[4], rW[2];
#pragma unroll
    for (int mt = 0; mt < 4; mt++) rA[mt] = warp_m * 64 + mt * 16 + (lane & 15);
#pragma unroll
    for (int nt2 = 0; nt2 < 2; nt2++) rW[nt2] = warp_n * 32 + nt2 * 16 + (lane & 15);
    const int khalf = lane >> 4;

    gstage(Ah, Al, M, rowTile, Wh, Wl, colTile, 0, sbase, tid);
    cp_commit();

    for (int c = 0; c < 16; c++) {
        if (c + 1 < 16) {
            gstage(Ah, Al, M, rowTile, Wh, Wl, colTile, (c + 1) * 64,
                   sbase + ((c + 1) & 1) * GT_BUF, tid);
            cp_commit();
            asm volatile("cp.async.wait_group 1;" ::: "memory");
        } else {
            asm volatile("cp.async.wait_group 0;" ::: "memory");
        }
        __syncthreads();

        const uint32_t bufb = sbase + (c & 1) * GT_BUF;
        const uint32_t sAh = bufb, sAl = bufb + GT_TILE;
        const uint32_t sWh = bufb + 2 * GT_TILE, sWl = bufb + 3 * GT_TILE;

#pragma unroll
        for (int kq = 0; kq < 4; kq++) {
            const int kp = 2 * kq + khalf;
            uint32_t ah[4][4], al[4][4], wh[2][4], wl[2][4];
#pragma unroll
            for (int mt = 0; mt < 4; mt++) {
                const uint32_t off = (rA[mt] << 7) + ((kp ^ (rA[mt] & 7)) << 4);
                ldm4(ah[mt], sAh + off);
                ldm4(al[mt], sAl + off);
            }
#pragma unroll
            for (int nt2 = 0; nt2 < 2; nt2++) {
                const uint32_t off = (rW[nt2] << 7) + ((kp ^ (rW[nt2] & 7)) << 4);
                ldm4(wh[nt2], sWh + off);
                ldm4(wl[nt2], sWl + off);
            }
            // term-major issue: acc reuse distance = 16 (kills RAW stalls)
#pragma unroll
            for (int term = 0; term < 3; term++) {
#pragma unroll
                for (int mt = 0; mt < 4; mt++) {
#pragma unroll
                    for (int nt = 0; nt < 4; nt++) {
                        const uint32_t* afrag = (term == 2) ? al[mt] : ah[mt];
                        const uint32_t* wfrag = (term == 1) ? wl[nt >> 1] : wh[nt >> 1];
                        mma16816(acc[mt][nt], afrag,
                                 wfrag[nt & 1], wfrag[(nt & 1) + 2]);
                    }
                }
            }
        }
        __syncthreads();
    }

    // epilogue
    const int g = lane >> 2, tg = lane & 3;
#pragma unroll
    for (int mt = 0; mt < 4; mt++) {
#pragma unroll
        for (int nt = 0; nt < 4; nt++) {
            const int n0 = colTile + warp_n * 32 + nt * 8 + tg * 2;
            const float2 bv = *(const float2*)(bias + n0);
#pragma unroll
            for (int hf = 0; hf < 2; hf++) {
                const int m = rowTile + warp_m * 64 + mt * 16 + g + hf * 8;
                if (m >= M) continue;
                float v0 = acc[mt][nt][hf * 2 + 0] + bv.x;
                float v1 = acc[mt][nt][hf * 2 + 1] + bv.y;
                if (MODE == 0) {
                    float2 o; o.x = v0; o.y = v1;
                    *(float2*)(outf + (long long)m * 1024 + n0) = o;
                } else {
                    int b_, nn;
                    if (MODE == 1) { b_ = m >> 11; nn = m & 2047; }
                    else           { b_ = m >> 4;  nn = NVID + (m & 15); }
                    const int hh = n0 >> 6, d = n0 & 63;
                    if (MODE == 1 && rk && d < 60) {
                        const int seg = d / 20, jj = (d - seg * 20) >> 1;
                        const int pos = (seg == 0) ? (nn >> 8)
                                      : (seg == 1) ? ((nn >> 4) & 15) : (nn & 15);
                        const float omega = ex2f(-(float)jj * 1.3287712379549449f);
                        float sn, cs;
                        sincosf((float)pos * omega, &sn, &cs);
                        const float x1 = v0 * cs - v1 * sn;
                        const float x2 = v1 * cs + v0 * sn;
                        v0 = x1; v1 = x2;
                    }
                    if (rk == 1) { v0 *= QSC; v1 *= QSC; }
                    unsigned short h0, l0_, h1, l1_;
                    bsplit(v0, h0, l0_); bsplit(v1, h1, l1_);
                    const long long idx = (((long long)(b_ * HEADS + hh)) * NTOT + nn) * HD + d;
                    *(ushort2*)(oh + idx) = make_ushort2(h0, h1);
                    *(ushort2*)(ol + idx) = make_ushort2(l0_, l1_);
                }
            }
        }
    }
}

// grid (8, 33, 3): z = {q,k,v}; by<32 video rows; by==32 action rows
__global__ __launch_bounds__(256, 1)
void gemm_qkv_mma(const float* bq, const float* bk, const float* bv,
                  const float* bqa, const float* bka, const float* bva)
{
    const int z = blockIdx.z;
    const bool act = (blockIdx.y == 32);
    const unsigned short* Ah = g_bh + (act ? OFF_ACTION : OFF_VIDEO);
    const unsigned short* Al = g_bl + (act ? OFF_ACTION : OFF_VIDEO);
    const int M = act ? (BSZ * NACT) : (BSZ * NVID);
    const int rowTile = act ? 0 : blockIdx.y * 128;
    const int colTile = blockIdx.x * 128;
    const int widx = z + (act ? 3 : 0);
    const unsigned short* Wh = g_bh + OFF_W + widx * WSZ;
    const unsigned short* Wl = g_bl + OFF_W + widx * WSZ;
    const float* bias = act ? (z == 0 ? bqa : (z == 1 ? bka : bva))
                            : (z == 0 ? bq : (z == 1 ? bk : bv));
    unsigned short *oh, *ol;
    int rk;
    if (z == 0)      { oh = g_qh; ol = g_ql; rk = 1; }
    else if (z == 1) { oh = g_kh; ol = g_kl; rk = 2; }
    else             { oh = g_vh; ol = g_vl; rk = 0; }
    if (act) gemm_body<2>(Ah, Al, M, rowTile, Wh, Wl, colTile, bias, nullptr, oh, ol, rk);
    else     gemm_body<1>(Ah, Al, M, rowTile, Wh, Wl, colTile, bias, nullptr, oh, ol, rk);
}

// grid (8, 17, 2): z = batch; by<16 video rows; by==16 action rows
__global__ __launch_bounds__(256, 1)
void gemm_out_mma(const float* bp, const float* bpa, float* __restrict__ dout)
{
    const int z = blockIdx.z;
    const bool act = (blockIdx.y == 16);
    const long long aoff = OFF_CTX + (long long)z * NTOT * HIDDEN +
                           (act ? (long long)NVID * HIDDEN : 0);
    const unsigned short* Ah = g_bh + aoff;
    const unsigned short* Al = g_bl + aoff;
    const int M = act ? NACT : NVID;
    const int rowTile = act ? 0 : blockIdx.y * 128;
    const int colTile = blockIdx.x * 128;
    const int widx = act ? 7 : 6;
    const unsigned short* Wh = g_bh + OFF_W + widx * WSZ;
    const unsigned short* Wl = g_bl + OFF_W + widx * WSZ;
    const float* bias = act ? bpa : bp;
    float* C = act ? (dout + (long long)BSZ * NVID * HIDDEN + (long long)z * NACT * HIDDEN)
                   : (dout + (long long)z * NVID * HIDDEN);
    gemm_body<0>(Ah, Al, M, rowTile, Wh, Wl, colTile, bias, C, nullptr, nullptr, 0);
}

// ================= flash attention on mma.sync =================
#define AT_TILE 16384
#define AT_BUF0 32768
#define AT_BUF1 (32768 + 65536)
#define AT_SMEM (32768 + 2 * 65536)   // Qh+Ql + 2 KV buffers = 160 KB

__device__ __forceinline__ void stage_kv(const unsigned short* Kh, const unsigned short* Kl,
                                         const unsigned short* Vh, const unsigned short* Vl,
                                         long long base, int kt, uint32_t bufb, int tid)
{
#pragma unroll
    for (int i = 0; i < 16; i++) {
        const int arr = i >> 2;
        const int t = ((i & 3) << 8) + tid;
        const int row = t >> 3, c = t & 7;
        const int key = kt * 128 + row;
        const uint32_t dst = bufb + arr * AT_TILE + (row << 7) + ((c ^ (row & 7)) << 4);
        const unsigned short* s =
            (arr == 0 ? Kh : arr == 1 ? Kl : arr == 2 ? Vh : Vl) +
            base + (long long)(key < NTOT ? key : 0) * HD + c * 8;
        cpa16z(dst, s, (key < NTOT) ? 16 : 0);
    }
}

__global__ __launch_bounds__(256, 1)
void attn_mma()
{
    extern __shared__ char dsm[];
    const uint32_t sb = smem_u32(dsm);
    const int tid = threadIdx.x, lane = tid & 31, w = tid >> 5;
    const int qt = blockIdx.x, bh = blockIdx.y;
    const int b = bh >> 4, h = bh & 15;
    const long long base = (long long)bh * NTOT * HD;
    const int g = lane >> 2, tg = lane & 3;

    // stage Q (hi/lo) + KV tile 0
#pragma unroll
    for (int i = 0; i < 8; i++) {
        const int arr = i >> 2;
        const int t = ((i & 3) << 8) + tid;
        const int row = t >> 3, c = t & 7;
        const int n = qt * 128 + row;
        const uint32_t dst = sb + arr * AT_TILE + (row << 7) + ((c ^ (row & 7)) << 4);
        const unsigned short* src = (arr == 0 ? g_qh : g_ql) +
                                    base + (long long)(n < NTOT ? n : 0) * HD + c * 8;
        cpa16z(dst, src, (n < NTOT) ? 16 : 0);
    }
    stage_kv(g_kh, g_kl, g_vh, g_vl, base, 0, sb + AT_BUF0, tid);
    cp_commit();

    float oacc[8][4];
#pragma unroll
    for (int i = 0; i < 8; i++)
#pragma unroll
        for (int j = 0; j < 4; j++) oacc[i][j] = 0.f;
    float m0 = -1e30f, m1 = -1e30f, l0 = 0.f, l1 = 0.f;
    uint32_t qfh[4][4], qfl[4][4];

    const int NKT = 17;
    for (int kt = 0; kt < NKT; kt++) {
        if (kt + 1 < NKT) {
            stage_kv(g_kh, g_kl, g_vh, g_vl, base, kt + 1,
                     sb + (((kt + 1) & 1) ? AT_BUF1 : AT_BUF0), tid);
            cp_commit();
            asm volatile("cp.async.wait_group 1;" ::: "memory");
        } else {
            asm volatile("cp.async.wait_group 0;" ::: "memory");
        }
        __syncthreads();

        if (kt == 0) {   // Q fragments (once)
            const int row = w * 16 + (lane & 15);
#pragma unroll
            for (int kq = 0; kq < 4; kq++) {
                const int kp = 2 * kq + (lane >> 4);
                const uint32_t off = (row << 7) + ((kp ^ (row & 7)) << 4);
                ldm4(qfh[kq], sb + off);
                ldm4(qfl[kq], sb + AT_TILE + off);
            }
        }

        const uint32_t bufb = sb + ((kt & 1) ? AT_BUF1 : AT_BUF0);
        const uint32_t sKh = bufb, sKl = bufb + AT_TILE;
        const uint32_t sVh = bufb + 2 * AT_TILE, sVl = bufb + 3 * AT_TILE;

        float sacc[16][4];
#pragma unroll
        for (int i = 0; i < 16; i++)
#pragma unroll
            for (int j = 0; j < 4; j++) sacc[i][j] = 0.f;

        // S = Q K^T : process key-row groups in pairs; issue 12 MMAs over 4 accs
#pragma unroll
        for (int kq = 0; kq < 4; kq++) {
            const int kp = 2 * kq + (lane >> 4);
#pragma unroll
            for (int ngp = 0; ngp < 4; ngp++) {
                const int rowa = (2 * ngp) * 16 + (lane & 15);
                const int rowb = (2 * ngp + 1) * 16 + (lane & 15);
                const uint32_t offa = (rowa << 7) + ((kp ^ (rowa & 7)) << 4);
                const uint32_t offb = (rowb << 7) + ((kp ^ (rowb & 7)) << 4);
                uint32_t kha[4], kla[4], khb[4], klb[4];
                ldm4(kha, sKh + offa);
                ldm4(khb, sKh + offb);
                ldm4(kla, sKl + offa);
                ldm4(klb, sKl + offb);
                float* a0 = sacc[4 * ngp + 0];
                float* a1 = sacc[4 * ngp + 1];
                float* a2 = sacc[4 * ngp + 2];
                float* a3 = sacc[4 * ngp + 3];
                mma16816(a0, qfh[kq], kha[0], kha[2]);
                mma16816(a1, qfh[kq], kha[1], kha[3]);
                mma16816(a2, qfh[kq], khb[0], khb[2]);
                mma16816(a3, qfh[kq], khb[1], khb[3]);
                mma16816(a0, qfh[kq], kla[0], kla[2]);
                mma16816(a1, qfh[kq], kla[1], kla[3]);
                mma16816(a2, qfh[kq], klb[0], klb[2]);
                mma16816(a3, qfh[kq], klb[1], klb[3]);
                mma16816(a0, qfl[kq], kha[0], kha[2]);
                mma16816(a1, qfl[kq], kha[1], kha[3]);
                mma16816(a2, qfl[kq], khb[0], khb[2]);
                mma16816(a3, qfl[kq], khb[1], khb[3]);
            }
        }

        // mask + online softmax (base-2)
        const int kvalid = NTOT - kt * 128;
        if (kvalid < 128) {
#pragma unroll
            for (int nt = 0; nt < 16; nt++) {
                const int c0 = nt * 8 + 2 * tg;
                if (c0 >= kvalid)     { sacc[nt][0] = -1e30f; sacc[nt][2] = -1e30f; }
                if (c0 + 1 >= kvalid) { sacc[nt][1] = -1e30f; sacc[nt][3] = -1e30f; }
            }
        }
        float mx0 = -1e30f, mx1 = -1e30f;
#pragma unroll
        for (int nt = 0; nt < 16; nt++) {
            mx0 = fmaxf(mx0, fmaxf(sacc[nt][0], sacc[nt][1]));
            mx1 = fmaxf(mx1, fmaxf(sacc[nt][2], sacc[nt][3]));
        }
        mx0 = fmaxf(mx0, __shfl_xor_sync(0xffffffffu, mx0, 1));
        mx0 = fmaxf(mx0, __shfl_xor_sync(0xffffffffu, mx0, 2));
        mx1 = fmaxf(mx1, __shfl_xor_sync(0xffffffffu, mx1, 1));
        mx1 = fmaxf(mx1, __shfl_xor_sync(0xffffffffu, mx1, 2));
        const float mn0 = fmaxf(m0, mx0), mn1 = fmaxf(m1, mx1);
        const float cr0 = ex2f(m0 - mn0), cr1 = ex2f(m1 - mn1);
        m0 = mn0; m1 = mn1;
        float s0 = 0.f, s1 = 0.f;
#pragma unroll
        for (int nt = 0; nt < 16; nt++) {
            sacc[nt][0] = ex2f(sacc[nt][0] - mn0);
            sacc[nt][1] = ex2f(sacc[nt][1] - mn0);
            sacc[nt][2] = ex2f(sacc[nt][2] - mn1);
            sacc[nt][3] = ex2f(sacc[nt][3] - mn1);
            s0 += sacc[nt][0] + sacc[nt][1];
            s1 += sacc[nt][2] + sacc[nt][3];
        }
        s0 += __shfl_xor_sync(0xffffffffu, s0, 1);
        s0 += __shfl_xor_sync(0xffffffffu, s0, 2);
        s1 += __shfl_xor_sync(0xffffffffu, s1, 1);
        s1 += __shfl_xor_sync(0xffffffffu, s1, 2);
        l0 = l0 * cr0 + s0; l1 = l1 * cr1 + s1;
#pragma unroll
        for (int nt = 0; nt < 8; nt++) {
            oacc[nt][0] *= cr0; oacc[nt][1] *= cr0;
            oacc[nt][2] *= cr1; oacc[nt][3] *= cr1;
        }

        // O += P V : column groups in pairs; 12 MMAs over 4 accs
#pragma unroll
        for (int kc = 0; kc < 8; kc++) {
            uint32_t pah[4], pal[4];
            const float* t0 = sacc[2 * kc];
            const float* t1 = sacc[2 * kc + 1];
            pah[0] = pkbf(t0[0], t0[1]);
            pah[1] = pkbf(t0[2], t0[3]);
            pah[2] = pkbf(t1[0], t1[1]);
            pah[3] = pkbf(t1[2], t1[3]);
#pragma unroll
            for (int u = 0; u < 4; u++) {
                const float* tt = (u < 2) ? t0 : t1;
                const float e0 = tt[(u & 1) * 2 + 0] - __uint_as_float(pah[u] << 16);
                const float e1 = tt[(u & 1) * 2 + 1] - __uint_as_float(pah[u] & 0xFFFF0000u);
                pal[u] = pkbf(e0, e1);
            }
            const int row = kc * 16 + (lane & 15);
#pragma unroll
            for (int ngp = 0; ngp < 2; ngp++) {
                const int cca = 2 * (2 * ngp) + (lane >> 4);
                const int ccb = 2 * (2 * ngp + 1) + (lane >> 4);
                const uint32_t offa = (row << 7) + ((cca ^ (row & 7)) << 4);
                const uint32_t offb = (row << 7) + ((ccb ^ (row & 7)) << 4);
                uint32_t vha[4], vla[4], vhb[4], vlb[4];
                ldm4t(vha, sVh + offa);
                ldm4t(vhb, sVh + offb);
                ldm4t(vla, sVl + offa);
                ldm4t(vlb, sVl + offb);
                float* a0 = oacc[4 * ngp + 0];
                float* a1 = oacc[4 * ngp + 1];
                float* a2 = oacc[4 * ngp + 2];
                float* a3 = oacc[4 * ngp + 3];
                mma16816(a0, pah, vha[0], vha[1]);
                mma16816(a1, pah, vha[2], vha[3]);
                mma16816(a2, pah, vhb[0], vhb[1]);
                mma16816(a3, pah, vhb[2], vhb[3]);
                mma16816(a0, pah, vla[0], vla[1]);
                mma16816(a1, pah, vla[2], vla[3]);
                mma16816(a2, pah, vlb[0], vlb[1]);
                mma16816(a3, pah, vlb[2], vlb[3]);
                mma16816(a0, pal, vha[0], vha[1]);
                mma16816(a1, pal, vha[2], vha[3]);
                mma16816(a2, pal, vhb[0], vhb[1]);
                mma16816(a3, pal, vhb[2], vhb[3]);
            }
        }
        __syncthreads();
    }

    // normalize + write ctx as bf16 hi/lo split (consumed by out-proj)
    const float iv0 = 1.f / l0, iv1 = 1.f / l1;
    const int n0 = qt * 128 + w * 16 + g;
    const int n1 = n0 + 8;
#pragma unroll
    for (int nt = 0; nt < 8; nt++) {
        const int d = nt * 8 + 2 * tg;
        if (n0 < NTOT) {
            unsigned short h0, l0_, h1, l1_;
            bsplit(oacc[nt][0] * iv0, h0, l0_);
            bsplit(oacc[nt][1] * iv0, h1, l1_);
            const long long idx = OFF_CTX + ((long long)(b * NTOT + n0)) * HIDDEN + h * HD + d;
            *(ushort2*)(g_bh + idx) = make_ushort2(h0, h1);
            *(ushort2*)(g_bl + idx) = make_ushort2(l0_, l1_);
        }
        if (n1 < NTOT) {
            unsigned short h0, l0_, h1, l1_;
            bsplit(oacc[nt][2] * iv1, h0, l0_);
            bsplit(oacc[nt][3] * iv1, h1, l1_);
            const long long idx = OFF_CTX + ((long long)(b * NTOT + n1)) * HIDDEN + h * HD + d;
            *(ushort2*)(g_bh + idx) = make_ushort2(h0, h1);
            *(ushort2*)(g_bl + idx) = make_ushort2(l0_, l1_);
        }
    }
}

// ---------------- host launcher ----------------
extern "C" void kernel_launch(void* const* d_in, const int* in_sizes, int n_in,
                              void* d_out, int out_size)
{
    (void)out_size;
    const float* video = nullptr;
    const float* action = nullptr;
    const float* wb[16];
    int wi = 0;
    for (int i = 0; i < n_in; i++) {
        const int sz = in_sizes[i];
        if (sz == BSZ * NVID * HIDDEN)       video  = (const float*)d_in[i];
        else if (sz == BSZ * NACT * HIDDEN)  action = (const float*)d_in[i];
        else if (wi < 16)                    wb[wi++] = (const float*)d_in[i];
    }
    float* out = (float*)d_out;

    cudaFuncSetAttribute(gemm_qkv_mma, cudaFuncAttributeMaxDynamicSharedMemorySize, GT_SMEM);
    cudaFuncSetAttribute(gemm_out_mma, cudaFuncAttributeMaxDynamicSharedMemorySize, GT_SMEM);
    cudaFuncSetAttribute(attn_mma, cudaFuncAttributeMaxDynamicSharedMemorySize, AT_SMEM);

    // split inputs + weights into bf16 hi/lo
    cvt_all<<<dim3(1024, 10), 256>>>(video, action, wb[0], wb[2], wb[4], wb[6],
                                     wb[8], wb[10], wb[12], wb[14]);

    // QKV projections (rope + scale + split fused in epilogue)
    gemm_qkv_mma<<<dim3(8, 33, 3), 256, GT_SMEM>>>(wb[1], wb[3], wb[5],
                                                   wb[7], wb[9], wb[11]);

    // attention on tensor cores
    attn_mma<<<dim3(17, 32), 256, AT_SMEM>>>();

    // output projection
    gemm_out_mma<<<dim3(8, 17, 2), 256, GT_SMEM>>>(wb[13], wb[15], out);
}

// round 8
// speedup vs baseline: 1.0479x; 1.0479x over previous
#include <cuda_runtime.h>
#include <cuda_bf16.h>
#include <cstdint>

#define HIDDEN 1024
#define HEADS 16
#define HD 64
#define NVID 2048
#define NACT 16
#define NTOT 2064
#define BSZ 2
#define BH (BSZ*HEADS)
// q pre-scale: ATT_SCALE * log2(e), so softmax uses exp2
#define QSC 0.18033688011112042f

#define WSZ 1048576LL
#define OFF_VIDEO 0LL
#define OFF_ACTION 4194304LL
#define OFF_W 4227072LL
#define OFF_CTX (OFF_W + 8LL * WSZ)
#define BF_TOTAL (OFF_CTX + 4227072LL)

// ---------------- scratch (device globals; no allocation allowed) ----------------
__device__ unsigned short g_bh[BF_TOTAL];    // bf16 hi: inputs, weights, ctx
__device__ unsigned short g_bl[BF_TOTAL];    // bf16 lo
__device__ unsigned short g_qh[BH * NTOT * HD], g_ql[BH * NTOT * HD];
__device__ unsigned short g_kh[BH * NTOT * HD], g_kl[BH * NTOT * HD];
__device__ unsigned short g_vh[BH * NTOT * HD], g_vl[BH * NTOT * HD];

// ---------------- helpers ----------------
__device__ __forceinline__ void cpa16z(uint32_t dst, const void* src, int bytes) {
    asm volatile("cp.async.cg.shared.global [%0], [%1], 16, %2;"
                 :: "r"(dst), "l"(src), "r"(bytes) : "memory");
}
__device__ __forceinline__ void cp_commit() {
    asm volatile("cp.async.commit_group;" ::: "memory");
}
__device__ __forceinline__ uint32_t smem_u32(const void* p) {
    return (uint32_t)__cvta_generic_to_shared(p);
}
__device__ __forceinline__ void ldm4(uint32_t* r, uint32_t addr) {
    asm volatile("ldmatrix.sync.aligned.m8n8.x4.shared.b16 {%0,%1,%2,%3}, [%4];"
                 : "=r"(r[0]), "=r"(r[1]), "=r"(r[2]), "=r"(r[3]) : "r"(addr));
}
__device__ __forceinline__ void ldm4t(uint32_t* r, uint32_t addr) {
    asm volatile("ldmatrix.sync.aligned.m8n8.x4.trans.shared.b16 {%0,%1,%2,%3}, [%4];"
                 : "=r"(r[0]), "=r"(r[1]), "=r"(r[2]), "=r"(r[3]) : "r"(addr));
}
__device__ __forceinline__ void mma16816(float* c, const uint32_t* a,
                                         uint32_t b0, uint32_t b1) {
    asm volatile("mma.sync.aligned.m16n8k16.row.col.f32.bf16.bf16.f32 "
                 "{%0,%1,%2,%3}, {%4,%5,%6,%7}, {%8,%9}, {%0,%1,%2,%3};"
                 : "+f"(c[0]), "+f"(c[1]), "+f"(c[2]), "+f"(c[3])
                 : "r"(a[0]), "r"(a[1]), "r"(a[2]), "r"(a[3]), "r"(b0), "r"(b1));
}
__device__ __forceinline__ void bsplit(float x, unsigned short& h, unsigned short& l) {
    __nv_bfloat16 hb = __float2bfloat16_rn(x);
    h = __bfloat16_as_ushort(hb);
    l = __bfloat16_as_ushort(__float2bfloat16_rn(x - __bfloat162float(hb)));
}
__device__ __forceinline__ uint32_t pkbf(float lo, float hi) {
    uint32_t r;
    asm("cvt.rn.bf16x2.f32 %0, %1, %2;" : "=r"(r) : "f"(hi), "f"(lo));
    return r;
}
__device__ __forceinline__ float ex2f(float x) {
    float y; asm("ex2.approx.ftz.f32 %0, %1;" : "=f"(y) : "f"(x)); return y;
}

// ---------------- fp32 -> bf16 hi/lo split (inputs + weights) ----------------
__global__ void cvt_all(const float* v, const float* a,
                        const float* w0, const float* w1, const float* w2,
                        const float* w3, const float* w4, const float* w5,
                        const float* w6, const float* w7)
{
    const float* srcs[10] = { v, a, w0, w1, w2, w3, w4, w5, w6, w7 };
    const long long offs[10] = { OFF_VIDEO, OFF_ACTION,
        OFF_W + 0 * WSZ, OFF_W + 1 * WSZ, OFF_W + 2 * WSZ, OFF_W + 3 * WSZ,
        OFF_W + 4 * WSZ, OFF_W + 5 * WSZ, OFF_W + 6 * WSZ, OFF_W + 7 * WSZ };
    const int cnts[10] = { 4194304, 32768, 1048576, 1048576, 1048576, 1048576,
                           1048576, 1048576, 1048576, 1048576 };
    const int z = blockIdx.y;
    const float4* src = (const float4*)srcs[z];
    ushort4* hi = (ushort4*)(g_bh + offs[z]);
    ushort4* lo = (ushort4*)(g_bl + offs[z]);
    const int n4 = cnts[z] >> 2;
    for (int i = blockIdx.x * blockDim.x + threadIdx.x; i < n4;
         i += gridDim.x * blockDim.x) {
        const float4 x = src[i];
        ushort4 h, l;
        bsplit(x.x, h.x, l.x); bsplit(x.y, h.y, l.y);
        bsplit(x.z, h.z, l.z); bsplit(x.w, h.w, l.w);
        hi[i] = h; lo[i] = l;
    }
}

// ================= mma.sync bf16x3 GEMM (projections), 512 threads =================
#define GT_TILE 16384
#define GT_BUF  (4 * GT_TILE)
#define GT_SMEM (2 * GT_BUF)

__device__ __forceinline__ void gstage(const unsigned short* Ah, const unsigned short* Al,
                                       int M, int rowTile,
                                       const unsigned short* Wh, const unsigned short* Wl,
                                       int colTile, int k0, uint32_t bufb, int tid)
{
#pragma unroll
    for (int i = 0; i < 8; i++) {
        const int tile = i >> 1;
        const int t = ((i & 1) << 9) + tid;     // 0..1023 per tile
        const int row = t >> 3, c = t & 7;
        const uint32_t dst = bufb + tile * GT_TILE + (row << 7) + ((c ^ (row & 7)) << 4);
        if (tile == 0 || tile == 1) {
            const int m = rowTile + row;
            const int mm = (m < M) ? m : 0;
            const unsigned short* s = (tile == 0 ? Ah : Al) + (long long)mm * 1024 + k0 + c * 8;
            cpa16z(dst, s, (m < M) ? 16 : 0);
        } else {
            const unsigned short* s = (tile == 2 ? Wh : Wl) +
                                      (long long)(colTile + row) * 1024 + k0 + c * 8;
            cpa16z(dst, s, 16);
        }
    }
}

// 16 warps, warp grid 4x4, warp tile 32x32.
// MODE 0: fp32 out[m*1024+n];  MODE 1: video qkv split+rope;  MODE 2: action qkv split
template <int MODE>
__device__ __forceinline__ void gemm_body(const unsigned short* Ah, const unsigned short* Al,
                                          int M, int rowTile,
                                          const unsigned short* Wh, const unsigned short* Wl,
                                          int colTile, const float* bias,
                                          float* __restrict__ outf,
                                          unsigned short* __restrict__ oh,
                                          unsigned short* __restrict__ ol, int rk)
{
    extern __shared__ char dsmem[];
    const uint32_t sbase = smem_u32(dsmem);
    const int tid = threadIdx.x;
    const int lane = tid & 31, wid = tid >> 5;
    const int warp_m = wid >> 2, warp_n = wid & 3;

    float acc[2][4][4];
#pragma unroll
    for (int a = 0; a < 2; a++)
#pragma unroll
        for (int b = 0; b < 4; b++)
#pragma unroll
            for (int c = 0; c < 4; c++) acc[a][b][c] = 0.f;

    int rA[2], rW[2];
#pragma unroll
    for (int mt = 0; mt < 2; mt++) rA[mt] = warp_m * 32 + mt * 16 + (lane & 15);
#pragma unroll
    for (int nt2 = 0; nt2 < 2; nt2++) rW[nt2] = warp_n * 32 + nt2 * 16 + (lane & 15);
    const int khalf = lane >> 4;

    gstage(Ah, Al, M, rowTile, Wh, Wl, colTile, 0, sbase, tid);
    cp_commit();

    for (int c = 0; c < 16; c++) {
        if (c + 1 < 16) {
            gstage(Ah, Al, M, rowTile, Wh, Wl, colTile, (c + 1) * 64,
                   sbase + ((c + 1) & 1) * GT_BUF, tid);
            cp_commit();
            asm volatile("cp.async.wait_group 1;" ::: "memory");
        } else {
            asm volatile("cp.async.wait_group 0;" ::: "memory");
        }
        __syncthreads();

        const uint32_t bufb = sbase + (c & 1) * GT_BUF;
        const uint32_t sAh = bufb, sAl = bufb + GT_TILE;
        const uint32_t sWh = bufb + 2 * GT_TILE, sWl = bufb + 3 * GT_TILE;

#pragma unroll
        for (int kq = 0; kq < 4; kq++) {
            const int kp = 2 * kq + khalf;
            uint32_t ah[2][4], al[2][4], wh[2][4], wl[2][4];
#pragma unroll
            for (int mt = 0; mt < 2; mt++) {
                const uint32_t off = (rA[mt] << 7) + ((kp ^ (rA[mt] & 7)) << 4);
                ldm4(ah[mt], sAh + off);
                ldm4(al[mt], sAl + off);
            }
#pragma unroll
            for (int nt2 = 0; nt2 < 2; nt2++) {
                const uint32_t off = (rW[nt2] << 7) + ((kp ^ (rW[nt2] & 7)) << 4);
                ldm4(wh[nt2], sWh + off);
                ldm4(wl[nt2], sWl + off);
            }
#pragma unroll
            for (int term = 0; term < 3; term++) {
#pragma unroll
                for (int mt = 0; mt < 2; mt++) {
#pragma unroll
                    for (int nt = 0; nt < 4; nt++) {
                        const uint32_t* afrag = (term == 2) ? al[mt] : ah[mt];
                        const uint32_t* wfrag = (term == 1) ? wl[nt >> 1] : wh[nt >> 1];
                        mma16816(acc[mt][nt], afrag,
                                 wfrag[nt & 1], wfrag[(nt & 1) + 2]);
                    }
                }
            }
        }
        __syncthreads();
    }

    // epilogue
    const int g = lane >> 2, tg = lane & 3;
#pragma unroll
    for (int mt = 0; mt < 2; mt++) {
#pragma unroll
        for (int nt = 0; nt < 4; nt++) {
            const int n0 = colTile + warp_n * 32 + nt * 8 + tg * 2;
            const float2 bv = *(const float2*)(bias + n0);
#pragma unroll
            for (int hf = 0; hf < 2; hf++) {
                const int m = rowTile + warp_m * 32 + mt * 16 + g + hf * 8;
                if (m >= M) continue;
                float v0 = acc[mt][nt][hf * 2 + 0] + bv.x;
                float v1 = acc[mt][nt][hf * 2 + 1] + bv.y;
                if (MODE == 0) {
                    float2 o; o.x = v0; o.y = v1;
                    *(float2*)(outf + (long long)m * 1024 + n0) = o;
                } else {
                    int b_, nn;
                    if (MODE == 1) { b_ = m >> 11; nn = m & 2047; }
                    else           { b_ = m >> 4;  nn = NVID + (m & 15); }
                    const int hh = n0 >> 6, d = n0 & 63;
                    if (MODE == 1 && rk && d < 60) {
                        const int seg = d / 20, jj = (d - seg * 20) >> 1;
                        const int pos = (seg == 0) ? (nn >> 8)
                                      : (seg == 1) ? ((nn >> 4) & 15) : (nn & 15);
                        const float omega = ex2f(-(float)jj * 1.3287712379549449f);
                        float sn, cs;
                        sincosf((float)pos * omega, &sn, &cs);
                        const float x1 = v0 * cs - v1 * sn;
                        const float x2 = v1 * cs + v0 * sn;
                        v0 = x1; v1 = x2;
                    }
                    if (rk == 1) { v0 *= QSC; v1 *= QSC; }
                    unsigned short h0, l0_, h1, l1_;
                    bsplit(v0, h0, l0_); bsplit(v1, h1, l1_);
                    const long long idx = (((long long)(b_ * HEADS + hh)) * NTOT + nn) * HD + d;
                    *(ushort2*)(oh + idx) = make_ushort2(h0, h1);
                    *(ushort2*)(ol + idx) = make_ushort2(l0_, l1_);
                }
            }
        }
    }
}

// grid (8, 33, 3): z = {q,k,v}; by<32 video rows; by==32 action rows
__global__ __launch_bounds__(512, 1)
void gemm_qkv_mma(const float* bq, const float* bk, const float* bv,
                  const float* bqa, const float* bka, const float* bva)
{
    const int z = blockIdx.z;
    const bool act = (blockIdx.y == 32);
    const unsigned short* Ah = g_bh + (act ? OFF_ACTION : OFF_VIDEO);
    const unsigned short* Al = g_bl + (act ? OFF_ACTION : OFF_VIDEO);
    const int M = act ? (BSZ * NACT) : (BSZ * NVID);
    const int rowTile = act ? 0 : blockIdx.y * 128;
    const int colTile = blockIdx.x * 128;
    const int widx = z + (act ? 3 : 0);
    const unsigned short* Wh = g_bh + OFF_W + widx * WSZ;
    const unsigned short* Wl = g_bl + OFF_W + widx * WSZ;
    const float* bias = act ? (z == 0 ? bqa : (z == 1 ? bka : bva))
                            : (z == 0 ? bq : (z == 1 ? bk : bv));
    unsigned short *oh, *ol;
    int rk;
    if (z == 0)      { oh = g_qh; ol = g_ql; rk = 1; }
    else if (z == 1) { oh = g_kh; ol = g_kl; rk = 2; }
    else             { oh = g_vh; ol = g_vl; rk = 0; }
    if (act) gemm_body<2>(Ah, Al, M, rowTile, Wh, Wl, colTile, bias, nullptr, oh, ol, rk);
    else     gemm_body<1>(Ah, Al, M, rowTile, Wh, Wl, colTile, bias, nullptr, oh, ol, rk);
}

// grid (8, 17, 2): z = batch; by<16 video rows; by==16 action rows
__global__ __launch_bounds__(512, 1)
void gemm_out_mma(const float* bp, const float* bpa, float* __restrict__ dout)
{
    const int z = blockIdx.z;
    const bool act = (blockIdx.y == 16);
    const long long aoff = OFF_CTX + (long long)z * NTOT * HIDDEN +
                           (act ? (long long)NVID * HIDDEN : 0);
    const unsigned short* Ah = g_bh + aoff;
    const unsigned short* Al = g_bl + aoff;
    const int M = act ? NACT : NVID;
    const int rowTile = act ? 0 : blockIdx.y * 128;
    const int colTile = blockIdx.x * 128;
    const int widx = act ? 7 : 6;
    const unsigned short* Wh = g_bh + OFF_W + widx * WSZ;
    const unsigned short* Wl = g_bl + OFF_W + widx * WSZ;
    const float* bias = act ? bpa : bp;
    float* C = act ? (dout + (long long)BSZ * NVID * HIDDEN + (long long)z * NACT * HIDDEN)
                   : (dout + (long long)z * NVID * HIDDEN);
    gemm_body<0>(Ah, Al, M, rowTile, Wh, Wl, colTile, bias, C, nullptr, nullptr, 0);
}

// ================= flash attention on mma.sync (pipelined ldmatrix) =================
#define AT_TILE 16384
#define AT_BUF0 32768
#define AT_BUF1 (32768 + 65536)
#define AT_SMEM (32768 + 2 * 65536)   // Qh+Ql + 2 KV buffers = 160 KB

__device__ __forceinline__ void stage_kv(const unsigned short* Kh, const unsigned short* Kl,
                                         const unsigned short* Vh, const unsigned short* Vl,
                                         long long base, int kt, uint32_t bufb, int tid)
{
#pragma unroll
    for (int i = 0; i < 16; i++) {
        const int arr = i >> 2;
        const int t = ((i & 3) << 8) + tid;
        const int row = t >> 3, c = t & 7;
        const int key = kt * 128 + row;
        const uint32_t dst = bufb + arr * AT_TILE + (row << 7) + ((c ^ (row & 7)) << 4);
        const unsigned short* s =
            (arr == 0 ? Kh : arr == 1 ? Kl : arr == 2 ? Vh : Vl) +
            base + (long long)(key < NTOT ? key : 0) * HD + c * 8;
        cpa16z(dst, s, (key < NTOT) ? 16 : 0);
    }
}

__global__ __launch_bounds__(256, 1)
void attn_mma()
{
    extern __shared__ char dsm[];
    const uint32_t sb = smem_u32(dsm);
    const int tid = threadIdx.x, lane = tid & 31, w = tid >> 5;
    const int qt = blockIdx.x, bh = blockIdx.y;
    const int b = bh >> 4, h = bh & 15;
    const long long base = (long long)bh * NTOT * HD;
    const int g = lane >> 2, tg = lane & 3;
    const int khalf = lane >> 4, l15 = lane & 15;

    // stage Q (hi/lo) + KV tile 0
#pragma unroll
    for (int i = 0; i < 8; i++) {
        const int arr = i >> 2;
        const int t = ((i & 3) << 8) + tid;
        const int row = t >> 3, c = t & 7;
        const int n = qt * 128 + row;
        const uint32_t dst = sb + arr * AT_TILE + (row << 7) + ((c ^ (row & 7)) << 4);
        const unsigned short* src = (arr == 0 ? g_qh : g_ql) +
                                    base + (long long)(n < NTOT ? n : 0) * HD + c * 8;
        cpa16z(dst, src, (n < NTOT) ? 16 : 0);
    }
    stage_kv(g_kh, g_kl, g_vh, g_vl, base, 0, sb + AT_BUF0, tid);
    cp_commit();

    float oacc[8][4];
#pragma unroll
    for (int i = 0; i < 8; i++)
#pragma unroll
        for (int j = 0; j < 4; j++) oacc[i][j] = 0.f;
    float m0 = -1e30f, m1 = -1e30f, l0 = 0.f, l1 = 0.f;
    uint32_t qfh[4][4], qfl[4][4];

    const int NKT = 17;
    for (int kt = 0; kt < NKT; kt++) {
        if (kt + 1 < NKT) {
            stage_kv(g_kh, g_kl, g_vh, g_vl, base, kt + 1,
                     sb + (((kt + 1) & 1) ? AT_BUF1 : AT_BUF0), tid);
            cp_commit();
            asm volatile("cp.async.wait_group 1;" ::: "memory");
        } else {
            asm volatile("cp.async.wait_group 0;" ::: "memory");
        }
        __syncthreads();

        if (kt == 0) {   // Q fragments (once)
            const int row = w * 16 + l15;
#pragma unroll
            for (int kq = 0; kq < 4; kq++) {
                const int kp = 2 * kq + khalf;
                const uint32_t off = (row << 7) + ((kp ^ (row & 7)) << 4);
                ldm4(qfh[kq], sb + off);
                ldm4(qfl[kq], sb + AT_TILE + off);
            }
        }

        const uint32_t bufb = sb + ((kt & 1) ? AT_BUF1 : AT_BUF0);
        const uint32_t sKh = bufb, sKl = bufb + AT_TILE;
        const uint32_t sVh = bufb + 2 * AT_TILE, sVl = bufb + 3 * AT_TILE;

        float sacc[16][4];
#pragma unroll
        for (int i = 0; i < 16; i++)
#pragma unroll
            for (int j = 0; j < 4; j++) sacc[i][j] = 0.f;

        // ---- S = Q K^T : pipelined fragment loads (it = kq*4 + ngp) ----
        // fragment buffer layout: [0..3]=kha [4..7]=khb [8..11]=kla [12..15]=klb
        uint32_t kf[2][16];
        {
            // load it=0
            const int rowa0 = l15, rowb0 = 16 + l15;
            const uint32_t offa0 = (rowa0 << 7) + (((0 + khalf) ^ (rowa0 & 7)) << 4);
            const uint32_t offb0 = (rowb0 << 7) + (((0 + khalf) ^ (rowb0 & 7)) << 4);
            ldm4(kf[0] + 0,  sKh + offa0);
            ldm4(kf[0] + 4,  sKh + offb0);
            ldm4(kf[0] + 8,  sKl + offa0);
            ldm4(kf[0] + 12, sKl + offb0);
        }
#pragma unroll
        for (int it = 0; it < 16; it++) {
            if (it + 1 < 16) {
                const int nkq = (it + 1) >> 2, nngp = (it + 1) & 3;
                const int kp = 2 * nkq + khalf;
                const int rowa = (2 * nngp) * 16 + l15;
                const int rowb = rowa + 16;
                const uint32_t offa = (rowa << 7) + ((kp ^ (rowa & 7)) << 4);
                const uint32_t offb = (rowb << 7) + ((kp ^ (rowb & 7)) << 4);
                uint32_t* nf = kf[(it + 1) & 1];
                ldm4(nf + 0,  sKh + offa);
                ldm4(nf + 4,  sKh + offb);
                ldm4(nf + 8,  sKl + offa);
                ldm4(nf + 12, sKl + offb);
            }
            const int kq = it >> 2, ngp = it & 3;
            const uint32_t* f = kf[it & 1];
            float* a0 = sacc[4 * ngp + 0];
            float* a1 = sacc[4 * ngp + 1];
            float* a2 = sacc[4 * ngp + 2];
            float* a3 = sacc[4 * ngp + 3];
            mma16816(a0, qfh[kq], f[0], f[2]);
            mma16816(a1, qfh[kq], f[1], f[3]);
            mma16816(a2, qfh[kq], f[4], f[6]);
            mma16816(a3, qfh[kq], f[5], f[7]);
            mma16816(a0, qfh[kq], f[8], f[10]);
            mma16816(a1, qfh[kq], f[9], f[11]);
            mma16816(a2, qfh[kq], f[12], f[14]);
            mma16816(a3, qfh[kq], f[13], f[15]);
            mma16816(a0, qfl[kq], f[0], f[2]);
            mma16816(a1, qfl[kq], f[1], f[3]);
            mma16816(a2, qfl[kq], f[4], f[6]);
            mma16816(a3, qfl[kq], f[5], f[7]);
        }

        // mask + online softmax (base-2)
        const int kvalid = NTOT - kt * 128;
        if (kvalid < 128) {
#pragma unroll
            for (int nt = 0; nt < 16; nt++) {
                const int c0 = nt * 8 + 2 * tg;
                if (c0 >= kvalid)     { sacc[nt][0] = -1e30f; sacc[nt][2] = -1e30f; }
                if (c0 + 1 >= kvalid) { sacc[nt][1] = -1e30f; sacc[nt][3] = -1e30f; }
            }
        }
        float mx0 = -1e30f, mx1 = -1e30f;
#pragma unroll
        for (int nt = 0; nt < 16; nt++) {
            mx0 = fmaxf(mx0, fmaxf(sacc[nt][0], sacc[nt][1]));
            mx1 = fmaxf(mx1, fmaxf(sacc[nt][2], sacc[nt][3]));
        }
        mx0 = fmaxf(mx0, __shfl_xor_sync(0xffffffffu, mx0, 1));
        mx0 = fmaxf(mx0, __shfl_xor_sync(0xffffffffu, mx0, 2));
        mx1 = fmaxf(mx1, __shfl_xor_sync(0xffffffffu, mx1, 1));
        mx1 = fmaxf(mx1, __shfl_xor_sync(0xffffffffu, mx1, 2));
        const float mn0 = fmaxf(m0, mx0), mn1 = fmaxf(m1, mx1);
        const float cr0 = ex2f(m0 - mn0), cr1 = ex2f(m1 - mn1);
        m0 = mn0; m1 = mn1;
        float s0 = 0.f, s1 = 0.f;
#pragma unroll
        for (int nt = 0; nt < 16; nt++) {
            sacc[nt][0] = ex2f(sacc[nt][0] - mn0);
            sacc[nt][1] = ex2f(sacc[nt][1] - mn0);
            sacc[nt][2] = ex2f(sacc[nt][2] - mn1);
            sacc[nt][3] = ex2f(sacc[nt][3] - mn1);
            s0 += sacc[nt][0] + sacc[nt][1];
            s1 += sacc[nt][2] + sacc[nt][3];
        }
        s0 += __shfl_xor_sync(0xffffffffu, s0, 1);
        s0 += __shfl_xor_sync(0xffffffffu, s0, 2);
        s1 += __shfl_xor_sync(0xffffffffu, s1, 1);
        s1 += __shfl_xor_sync(0xffffffffu, s1, 2);
        l0 = l0 * cr0 + s0; l1 = l1 * cr1 + s1;
#pragma unroll
        for (int nt = 0; nt < 8; nt++) {
            oacc[nt][0] *= cr0; oacc[nt][1] *= cr0;
            oacc[nt][2] *= cr1; oacc[nt][3] *= cr1;
        }

        // ---- O += P V : pipelined fragment loads (it = kc*2 + ngp) ----
        // fragment buffer layout: [0..3]=vha [4..7]=vhb [8..11]=vla [12..15]=vlb
        uint32_t vf[2][16];
        {
            const int row0 = l15;
            const int cca0 = khalf, ccb0 = 2 + khalf;
            const uint32_t offa0 = (row0 << 7) + ((cca0 ^ (row0 & 7)) << 4);
            const uint32_t offb0 = (row0 << 7) + ((ccb0 ^ (row0 & 7)) << 4);
            ldm4t(vf[0] + 0,  sVh + offa0);
            ldm4t(vf[0] + 4,  sVh + offb0);
            ldm4t(vf[0] + 8,  sVl + offa0);
            ldm4t(vf[0] + 12, sVl + offb0);
        }
        uint32_t pah[4], pal[4];
#pragma unroll
        for (int it = 0; it < 16; it++) {
            if (it + 1 < 16) {
                const int nkc = (it + 1) >> 1, nngp = (it + 1) & 1;
                const int row = nkc * 16 + l15;
                const int cca = 4 * nngp + khalf, ccb = cca + 2;
                const uint32_t offa = (row << 7) + ((cca ^ (row & 7)) << 4);
                const uint32_t offb = (row << 7) + ((ccb ^ (row & 7)) << 4);
                uint32_t* nf = vf[(it + 1) & 1];
                ldm4t(nf + 0,  sVh + offa);
                ldm4t(nf + 4,  sVh + offb);
                ldm4t(nf + 8,  sVl + offa);
                ldm4t(nf + 12, sVl + offb);
            }
            const int kc = it >> 1, ngp = it & 1;
            if (ngp == 0) {   // pack P for this kc
                const float* t0 = sacc[2 * kc];
                const float* t1 = sacc[2 * kc + 1];
                pah[0] = pkbf(t0[0], t0[1]);
                pah[1] = pkbf(t0[2], t0[3]);
                pah[2] = pkbf(t1[0], t1[1]);
                pah[3] = pkbf(t1[2], t1[3]);
#pragma unroll
                for (int u = 0; u < 4; u++) {
                    const float* tt = (u < 2) ? t0 : t1;
                    const float e0 = tt[(u & 1) * 2 + 0] - __uint_as_float(pah[u] << 16);
                    const float e1 = tt[(u & 1) * 2 + 1] - __uint_as_float(pah[u] & 0xFFFF0000u);
                    pal[u] = pkbf(e0, e1);
                }
            }
            const uint32_t* f = vf[it & 1];
            float* a0 = oacc[4 * ngp + 0];
            float* a1 = oacc[4 * ngp + 1];
            float* a2 = oacc[4 * ngp + 2];
            float* a3 = oacc[4 * ngp + 3];
            mma16816(a0, pah, f[0], f[1]);
            mma16816(a1, pah, f[2], f[3]);
            mma16816(a2, pah, f[4], f[5]);
            mma16816(a3, pah, f[6], f[7]);
            mma16816(a0, pah, f[8], f[9]);
            mma16816(a1, pah, f[10], f[11]);
            mma16816(a2, pah, f[12], f[13]);
            mma16816(a3, pah, f[14], f[15]);
            mma16816(a0, pal, f[0], f[1]);
            mma16816(a1, pal, f[2], f[3]);
            mma16816(a2, pal, f[4], f[5]);
            mma16816(a3, pal, f[6], f[7]);
        }
        __syncthreads();
    }

    // normalize + write ctx as bf16 hi/lo split (consumed by out-proj)
    const float iv0 = 1.f / l0, iv1 = 1.f / l1;
    const int n0 = qt * 128 + w * 16 + g;
    const int n1 = n0 + 8;
#pragma unroll
    for (int nt = 0; nt < 8; nt++) {
        const int d = nt * 8 + 2 * tg;
        if (n0 < NTOT) {
            unsigned short h0, l0_, h1, l1_;
            bsplit(oacc[nt][0] * iv0, h0, l0_);
            bsplit(oacc[nt][1] * iv0, h1, l1_);
            const long long idx = OFF_CTX + ((long long)(b * NTOT + n0)) * HIDDEN + h * HD + d;
            *(ushort2*)(g_bh + idx) = make_ushort2(h0, h1);
            *(ushort2*)(g_bl + idx) = make_ushort2(l0_, l1_);
        }
        if (n1 < NTOT) {
            unsigned short h0, l0_, h1, l1_;
            bsplit(oacc[nt][2] * iv1, h0, l0_);
            bsplit(oacc[nt][3] * iv1, h1, l1_);
            const long long idx = OFF_CTX + ((long long)(b * NTOT + n1)) * HIDDEN + h * HD + d;
            *(ushort2*)(g_bh + idx) = make_ushort2(h0, h1);
            *(ushort2*)(g_bl + idx) = make_ushort2(l0_, l1_);
        }
    }
}

// ---------------- host launcher ----------------
extern "C" void kernel_launch(void* const* d_in, const int* in_sizes, int n_in,
                              void* d_out, int out_size)
{
    (void)out_size;
    const float* video = nullptr;
    const float* action = nullptr;
    const float* wb[16];
    int wi = 0;
    for (int i = 0; i < n_in; i++) {
        const int sz = in_sizes[i];
        if (sz == BSZ * NVID * HIDDEN)       video  = (const float*)d_in[i];
        else if (sz == BSZ * NACT * HIDDEN)  action = (const float*)d_in[i];
        else if (wi < 16)                    wb[wi++] = (const float*)d_in[i];
    }
    float* out = (float*)d_out;

    cudaFuncSetAttribute(gemm_qkv_mma, cudaFuncAttributeMaxDynamicSharedMemorySize, GT_SMEM);
    cudaFuncSetAttribute(gemm_out_mma, cudaFuncAttributeMaxDynamicSharedMemorySize, GT_SMEM);
    cudaFuncSetAttribute(attn_mma, cudaFuncAttributeMaxDynamicSharedMemorySize, AT_SMEM);

    // split inputs + weights into bf16 hi/lo
    cvt_all<<<dim3(1024, 10), 256>>>(video, action, wb[0], wb[2], wb[4], wb[6],
                                     wb[8], wb[10], wb[12], wb[14]);

    // QKV projections (rope + scale + split fused in epilogue), 512 thr/CTA
    gemm_qkv_mma<<<dim3(8, 33, 3), 512, GT_SMEM>>>(wb[1], wb[3], wb[5],
                                                   wb[7], wb[9], wb[11]);

    // attention on tensor cores (pipelined ldmatrix)
    attn_mma<<<dim3(17, 32), 256, AT_SMEM>>>();

    // output projection, 512 thr/CTA
    gemm_out_mma<<<dim3(8, 17, 2), 512, GT_SMEM>>>(wb[13], wb[15], out);
}

// round 9
// speedup vs baseline: 1.3905x; 1.3269x over previous
#include <cuda_runtime.h>
#include <cuda_fp16.h>
#include <cstdint>

#define HIDDEN 1024
#define HEADS 16
#define HD 64
#define NVID 2048
#define NACT 16
#define NTOT 2064
#define BSZ 2
#define BH (BSZ*HEADS)
// q pre-scale: ATT_SCALE * log2(e), so softmax uses exp2
#define QSC 0.18033688011112042f

#define WSZ 1048576LL
#define OFF_VIDEO 0LL
#define OFF_ACTION 4194304LL
#define OFF_W 4227072LL
#define OFF_CTX (OFF_W + 8LL * WSZ)
#define BF_TOTAL (OFF_CTX + 4227072LL)

// ---------------- scratch (device globals; no allocation allowed) ----------------
__device__ unsigned short g_bh[BF_TOTAL];    // fp16 hi: inputs, weights, ctx
__device__ unsigned short g_bl[BF_TOTAL];    // fp16 lo (weights only)
__device__ unsigned short g_qh[BH * NTOT * HD];
__device__ unsigned short g_kh[BH * NTOT * HD], g_kl[BH * NTOT * HD];
__device__ unsigned short g_vh[BH * NTOT * HD], g_vl[BH * NTOT * HD];

// ---------------- helpers ----------------
__device__ __forceinline__ void cpa16z(uint32_t dst, const void* src, int bytes) {
    asm volatile("cp.async.cg.shared.global [%0], [%1], 16, %2;"
                 :: "r"(dst), "l"(src), "r"(bytes) : "memory");
}
__device__ __forceinline__ void cp_commit() {
    asm volatile("cp.async.commit_group;" ::: "memory");
}
__device__ __forceinline__ uint32_t smem_u32(const void* p) {
    return (uint32_t)__cvta_generic_to_shared(p);
}
__device__ __forceinline__ void ldm4(uint32_t* r, uint32_t addr) {
    asm volatile("ldmatrix.sync.aligned.m8n8.x4.shared.b16 {%0,%1,%2,%3}, [%4];"
                 : "=r"(r[0]), "=r"(r[1]), "=r"(r[2]), "=r"(r[3]) : "r"(addr));
}
__device__ __forceinline__ void ldm4t(uint32_t* r, uint32_t addr) {
    asm volatile("ldmatrix.sync.aligned.m8n8.x4.trans.shared.b16 {%0,%1,%2,%3}, [%4];"
                 : "=r"(r[0]), "=r"(r[1]), "=r"(r[2]), "=r"(r[3]) : "r"(addr));
}
__device__ __forceinline__ void mma16816(float* c, const uint32_t* a,
                                         uint32_t b0, uint32_t b1) {
    asm volatile("mma.sync.aligned.m16n8k16.row.col.f32.f16.f16.f32 "
                 "{%0,%1,%2,%3}, {%4,%5,%6,%7}, {%8,%9}, {%0,%1,%2,%3};"
                 : "+f"(c[0]), "+f"(c[1]), "+f"(c[2]), "+f"(c[3])
                 : "r"(a[0]), "r"(a[1]), "r"(a[2]), "r"(a[3]), "r"(b0), "r"(b1));
}
__device__ __forceinline__ void hsplit(float x, unsigned short& h, unsigned short& l) {
    __half hb = __float2half_rn(x);
    h = __half_as_ushort(hb);
    l = __half_as_ushort(__float2half_rn(x - __half2float(hb)));
}
__device__ __forceinline__ unsigned short h16(float x) {
    return __half_as_ushort(__float2half_rn(x));
}
__device__ __forceinline__ uint32_t pkh(float lo, float hi) {
    uint32_t r;
    asm("cvt.rn.f16x2.f32 %0, %1, %2;" : "=r"(r) : "f"(hi), "f"(lo));
    return r;
}
__device__ __forceinline__ float ex2f(float x) {
    float y; asm("ex2.approx.ftz.f32 %0, %1;" : "=f"(y) : "f"(x)); return y;
}

// ---------------- fp32 -> fp16 hi/lo split (inputs + weights) ----------------
// lo parts written only for weights (z >= 2); activations use hi only.
__global__ void cvt_all(const float* v, const float* a,
                        const float* w0, const float* w1, const float* w2,
                        const float* w3, const float* w4, const float* w5,
                        const float* w6, const float* w7)
{
    const float* srcs[10] = { v, a, w0, w1, w2, w3, w4, w5, w6, w7 };
    const long long offs[10] = { OFF_VIDEO, OFF_ACTION,
        OFF_W + 0 * WSZ, OFF_W + 1 * WSZ, OFF_W + 2 * WSZ, OFF_W + 3 * WSZ,
        OFF_W + 4 * WSZ, OFF_W + 5 * WSZ, OFF_W + 6 * WSZ, OFF_W + 7 * WSZ };
    const int cnts[10] = { 4194304, 32768, 1048576, 1048576, 1048576, 1048576,
                           1048576, 1048576, 1048576, 1048576 };
    const int z = blockIdx.y;
    const float4* src = (const float4*)srcs[z];
    ushort4* hi = (ushort4*)(g_bh + offs[z]);
    ushort4* lo = (ushort4*)(g_bl + offs[z]);
    const bool wlo = (z >= 2);
    const int n4 = cnts[z] >> 2;
    for (int i = blockIdx.x * blockDim.x + threadIdx.x; i < n4;
         i += gridDim.x * blockDim.x) {
        const float4 x = src[i];
        ushort4 h, l;
        hsplit(x.x, h.x, l.x); hsplit(x.y, h.y, l.y);
        hsplit(x.z, h.z, l.z); hsplit(x.w, h.w, l.w);
        hi[i] = h;
        if (wlo) lo[i] = l;
    }
}

// ================= mma.sync fp16x2 GEMM (projections), 512 threads =================
// C = Ah * (Wh + Wl): 2 MMA terms, 3 staged tiles (Ah, Wh, Wl)
#define GT_TILE 16384
#define GT_BUF  (3 * GT_TILE)
#define GT_SMEM (2 * GT_BUF)          // 96 KB

__device__ __forceinline__ void gstage(const unsigned short* Ah,
                                       int M, int rowTile,
                                       const unsigned short* Wh, const unsigned short* Wl,
                                       int colTile, int k0, uint32_t bufb, int tid)
{
#pragma unroll
    for (int i = 0; i < 6; i++) {
        const int tile = i >> 1;
        const int t = ((i & 1) << 9) + tid;     // 0..1023 per tile
        const int row = t >> 3, c = t & 7;
        const uint32_t dst = bufb + tile * GT_TILE + (row << 7) + ((c ^ (row & 7)) << 4);
        if (tile == 0) {
            const int m = rowTile + row;
            const int mm = (m < M) ? m : 0;
            const unsigned short* s = Ah + (long long)mm * 1024 + k0 + c * 8;
            cpa16z(dst, s, (m < M) ? 16 : 0);
        } else {
            const unsigned short* s = (tile == 1 ? Wh : Wl) +
                                      (long long)(colTile + row) * 1024 + k0 + c * 8;
            cpa16z(dst, s, 16);
        }
    }
}

// 16 warps, warp grid 4x4, warp tile 32x32.
// MODE 0: fp32 out[m*1024+n];  MODE 1: video qkv split+rope;  MODE 2: action qkv split
template <int MODE>
__device__ __forceinline__ void gemm_body(const unsigned short* Ah,
                                          int M, int rowTile,
                                          const unsigned short* Wh, const unsigned short* Wl,
                                          int colTile, const float* bias,
                                          float* __restrict__ outf,
                                          unsigned short* __restrict__ oh,
                                          unsigned short* __restrict__ ol, int rk)
{
    extern __shared__ char dsmem[];
    const uint32_t sbase = smem_u32(dsmem);
    const int tid = threadIdx.x;
    const int lane = tid & 31, wid = tid >> 5;
    const int warp_m = wid >> 2, warp_n = wid & 3;

    float acc[2][4][4];
#pragma unroll
    for (int a = 0; a < 2; a++)
#pragma unroll
        for (int b = 0; b < 4; b++)
#pragma unroll
            for (int c = 0; c < 4; c++) acc[a][b][c] = 0.f;

    int rA[2], rW[2];
#pragma unroll
    for (int mt = 0; mt < 2; mt++) rA[mt] = warp_m * 32 + mt * 16 + (lane & 15);
#pragma unroll
    for (int nt2 = 0; nt2 < 2; nt2++) rW[nt2] = warp_n * 32 + nt2 * 16 + (lane & 15);
    const int khalf = lane >> 4;

    gstage(Ah, M, rowTile, Wh, Wl, colTile, 0, sbase, tid);
    cp_commit();

    for (int c = 0; c < 16; c++) {
        if (c + 1 < 16) {
            gstage(Ah, M, rowTile, Wh, Wl, colTile, (c + 1) * 64,
                   sbase + ((c + 1) & 1) * GT_BUF, tid);
            cp_commit();
            asm volatile("cp.async.wait_group 1;" ::: "memory");
        } else {
            asm volatile("cp.async.wait_group 0;" ::: "memory");
        }
        __syncthreads();

        const uint32_t bufb = sbase + (c & 1) * GT_BUF;
        const uint32_t sAh = bufb;
        const uint32_t sWh = bufb + GT_TILE, sWl = bufb + 2 * GT_TILE;

#pragma unroll
        for (int kq = 0; kq < 4; kq++) {
            const int kp = 2 * kq + khalf;
            uint32_t ah[2][4], wh[2][4], wl[2][4];
#pragma unroll
            for (int mt = 0; mt < 2; mt++) {
                const uint32_t off = (rA[mt] << 7) + ((kp ^ (rA[mt] & 7)) << 4);
                ldm4(ah[mt], sAh + off);
            }
#pragma unroll
            for (int nt2 = 0; nt2 < 2; nt2++) {
                const uint32_t off = (rW[nt2] << 7) + ((kp ^ (rW[nt2] & 7)) << 4);
                ldm4(wh[nt2], sWh + off);
                ldm4(wl[nt2], sWl + off);
            }
#pragma unroll
            for (int term = 0; term < 2; term++) {
#pragma unroll
                for (int mt = 0; mt < 2; mt++) {
#pragma unroll
                    for (int nt = 0; nt < 4; nt++) {
                        const uint32_t* wfrag = (term == 1) ? wl[nt >> 1] : wh[nt >> 1];
                        mma16816(acc[mt][nt], ah[mt],
                                 wfrag[nt & 1], wfrag[(nt & 1) + 2]);
                    }
                }
            }
        }
        __syncthreads();
    }

    // epilogue
    const int g = lane >> 2, tg = lane & 3;
#pragma unroll
    for (int mt = 0; mt < 2; mt++) {
#pragma unroll
        for (int nt = 0; nt < 4; nt++) {
            const int n0 = colTile + warp_n * 32 + nt * 8 + tg * 2;
            const float2 bv = *(const float2*)(bias + n0);
#pragma unroll
            for (int hf = 0; hf < 2; hf++) {
                const int m = rowTile + warp_m * 32 + mt * 16 + g + hf * 8;
                if (m >= M) continue;
                float v0 = acc[mt][nt][hf * 2 + 0] + bv.x;
                float v1 = acc[mt][nt][hf * 2 + 1] + bv.y;
                if (MODE == 0) {
                    float2 o; o.x = v0; o.y = v1;
                    *(float2*)(outf + (long long)m * 1024 + n0) = o;
                } else {
                    int b_, nn;
                    if (MODE == 1) { b_ = m >> 11; nn = m & 2047; }
                    else           { b_ = m >> 4;  nn = NVID + (m & 15); }
                    const int hh = n0 >> 6, d = n0 & 63;
                    if (MODE == 1 && rk && d < 60) {
                        const int seg = d / 20, jj = (d - seg * 20) >> 1;
                        const int pos = (seg == 0) ? (nn >> 8)
                                      : (seg == 1) ? ((nn >> 4) & 15) : (nn & 15);
                        const float omega = ex2f(-(float)jj * 1.3287712379549449f);
                        float sn, cs;
                        sincosf((float)pos * omega, &sn, &cs);
                        const float x1 = v0 * cs - v1 * sn;
                        const float x2 = v1 * cs + v0 * sn;
                        v0 = x1; v1 = x2;
                    }
                    const long long idx = (((long long)(b_ * HEADS + hh)) * NTOT + nn) * HD + d;
                    if (rk == 1) {       // q: scaled, hi only
                        v0 *= QSC; v1 *= QSC;
                        *(ushort2*)(oh + idx) = make_ushort2(h16(v0), h16(v1));
                    } else {             // k, v: hi + lo split
                        unsigned short h0, l0_, h1, l1_;
                        hsplit(v0, h0, l0_); hsplit(v1, h1, l1_);
                        *(ushort2*)(oh + idx) = make_ushort2(h0, h1);
                        *(ushort2*)(ol + idx) = make_ushort2(l0_, l1_);
                    }
                }
            }
        }
    }
}

// grid (8, 33, 3): z = {q,k,v}; by<32 video rows; by==32 action rows
__global__ __launch_bounds__(512, 1)
void gemm_qkv_mma(const float* bq, const float* bk, const float* bv,
                  const float* bqa, const float* bka, const float* bva)
{
    const int z = blockIdx.z;
    const bool act = (blockIdx.y == 32);
    const unsigned short* Ah = g_bh + (act ? OFF_ACTION : OFF_VIDEO);
    const int M = act ? (BSZ * NACT) : (BSZ * NVID);
    const int rowTile = act ? 0 : blockIdx.y * 128;
    const int colTile = blockIdx.x * 128;
    const int widx = z + (act ? 3 : 0);
    const unsigned short* Wh = g_bh + OFF_W + widx * WSZ;
    const unsigned short* Wl = g_bl + OFF_W + widx * WSZ;
    const float* bias = act ? (z == 0 ? bqa : (z == 1 ? bka : bva))
                            : (z == 0 ? bq : (z == 1 ? bk : bv));
    unsigned short *oh, *ol;
    int rk;
    if (z == 0)      { oh = g_qh; ol = nullptr; rk = 1; }
    else if (z == 1) { oh = g_kh; ol = g_kl; rk = 2; }
    else             { oh = g_vh; ol = g_vl; rk = 0; }
    if (act) gemm_body<2>(Ah, M, rowTile, Wh, Wl, colTile, bias, nullptr, oh, ol, rk);
    else     gemm_body<1>(Ah, M, rowTile, Wh, Wl, colTile, bias, nullptr, oh, ol, rk);
}

// grid (8, 17, 2): z = batch; by<16 video rows; by==16 action rows
__global__ __launch_bounds__(512, 1)
void gemm_out_mma(const float* bp, const float* bpa, float* __restrict__ dout)
{
    const int z = blockIdx.z;
    const bool act = (blockIdx.y == 16);
    const long long aoff = OFF_CTX + (long long)z * NTOT * HIDDEN +
                           (act ? (long long)NVID * HIDDEN : 0);
    const unsigned short* Ah = g_bh + aoff;
    const int M = act ? NACT : NVID;
    const int rowTile = act ? 0 : blockIdx.y * 128;
    const int colTile = blockIdx.x * 128;
    const int widx = act ? 7 : 6;
    const unsigned short* Wh = g_bh + OFF_W + widx * WSZ;
    const unsigned short* Wl = g_bl + OFF_W + widx * WSZ;
    const float* bias = act ? bpa : bp;
    float* C = act ? (dout + (long long)BSZ * NVID * HIDDEN + (long long)z * NACT * HIDDEN)
                   : (dout + (long long)z * NVID * HIDDEN);
    gemm_body<0>(Ah, M, rowTile, Wh, Wl, colTile, bias, C, nullptr, nullptr, 0);
}

// ================= flash attention on mma.sync (fp16 2-term) =================
// S = Qh*(Kh+Kl), O = Ph*(Vh+Vl)
#define AT_TILE 16384
#define AT_BUF0 16384
#define AT_BUF1 (16384 + 65536)
#define AT_SMEM (16384 + 2 * 65536)   // Qh + 2 KV buffers = 144 KB

__device__ __forceinline__ void stage_kv(const unsigned short* Kh, const unsigned short* Kl,
                                         const unsigned short* Vh, const unsigned short* Vl,
                                         long long base, int kt, uint32_t bufb, int tid)
{
#pragma unroll
    for (int i = 0; i < 16; i++) {
        const int arr = i >> 2;
        const int t = ((i & 3) << 8) + tid;
        const int row = t >> 3, c = t & 7;
        const int key = kt * 128 + row;
        const uint32_t dst = bufb + arr * AT_TILE + (row << 7) + ((c ^ (row & 7)) << 4);
        const unsigned short* s =
            (arr == 0 ? Kh : arr == 1 ? Kl : arr == 2 ? Vh : Vl) +
            base + (long long)(key < NTOT ? key : 0) * HD + c * 8;
        cpa16z(dst, s, (key < NTOT) ? 16 : 0);
    }
}

__global__ __launch_bounds__(256, 1)
void attn_mma()
{
    extern __shared__ char dsm[];
    const uint32_t sb = smem_u32(dsm);
    const int tid = threadIdx.x, lane = tid & 31, w = tid >> 5;
    const int qt = blockIdx.x, bh = blockIdx.y;
    const int b = bh >> 4, h = bh & 15;
    const long long base = (long long)bh * NTOT * HD;
    const int g = lane >> 2, tg = lane & 3;
    const int khalf = lane >> 4, l15 = lane & 15;

    // stage Q (hi only) + KV tile 0
#pragma unroll
    for (int i = 0; i < 4; i++) {
        const int t = (i << 8) + tid;
        const int row = t >> 3, c = t & 7;
        const int n = qt * 128 + row;
        const uint32_t dst = sb + (row << 7) + ((c ^ (row & 7)) << 4);
        const unsigned short* src = g_qh + base + (long long)(n < NTOT ? n : 0) * HD + c * 8;
        cpa16z(dst, src, (n < NTOT) ? 16 : 0);
    }
    stage_kv(g_kh, g_kl, g_vh, g_vl, base, 0, sb + AT_BUF0, tid);
    cp_commit();

    float oacc[8][4];
#pragma unroll
    for (int i = 0; i < 8; i++)
#pragma unroll
        for (int j = 0; j < 4; j++) oacc[i][j] = 0.f;
    float m0 = -1e30f, m1 = -1e30f, l0 = 0.f, l1 = 0.f;
    uint32_t qfh[4][4];

    const int NKT = 17;
    for (int kt = 0; kt < NKT; kt++) {
        if (kt + 1 < NKT) {
            stage_kv(g_kh, g_kl, g_vh, g_vl, base, kt + 1,
                     sb + (((kt + 1) & 1) ? AT_BUF1 : AT_BUF0), tid);
            cp_commit();
            asm volatile("cp.async.wait_group 1;" ::: "memory");
        } else {
            asm volatile("cp.async.wait_group 0;" ::: "memory");
        }
        __syncthreads();

        if (kt == 0) {   // Q fragments (once)
            const int row = w * 16 + l15;
#pragma unroll
            for (int kq = 0; kq < 4; kq++) {
                const int kp = 2 * kq + khalf;
                const uint32_t off = (row << 7) + ((kp ^ (row & 7)) << 4);
                ldm4(qfh[kq], sb + off);
            }
        }

        const uint32_t bufb = sb + ((kt & 1) ? AT_BUF1 : AT_BUF0);
        const uint32_t sKh = bufb, sKl = bufb + AT_TILE;
        const uint32_t sVh = bufb + 2 * AT_TILE, sVl = bufb + 3 * AT_TILE;

        float sacc[16][4];
#pragma unroll
        for (int i = 0; i < 16; i++)
#pragma unroll
            for (int j = 0; j < 4; j++) sacc[i][j] = 0.f;

        // ---- S = Qh*(Kh+Kl) : pipelined fragment loads (it = kq*4 + ngp) ----
        // fragment layout: [0..3]=kha [4..7]=khb [8..11]=kla [12..15]=klb
        uint32_t kf[2][16];
        {
            const int rowa0 = l15, rowb0 = 16 + l15;
            const uint32_t offa0 = (rowa0 << 7) + ((khalf ^ (rowa0 & 7)) << 4);
            const uint32_t offb0 = (rowb0 << 7) + ((khalf ^ (rowb0 & 7)) << 4);
            ldm4(kf[0] + 0,  sKh + offa0);
            ldm4(kf[0] + 4,  sKh + offb0);
            ldm4(kf[0] + 8,  sKl + offa0);
            ldm4(kf[0] + 12, sKl + offb0);
        }
#pragma unroll
        for (int it = 0; it < 16; it++) {
            if (it + 1 < 16) {
                const int nkq = (it + 1) >> 2, nngp = (it + 1) & 3;
                const int kp = 2 * nkq + khalf;
                const int rowa = (2 * nngp) * 16 + l15;
                const int rowb = rowa + 16;
                const uint32_t offa = (rowa << 7) + ((kp ^ (rowa & 7)) << 4);
                const uint32_t offb = (rowb << 7) + ((kp ^ (rowb & 7)) << 4);
                uint32_t* nf = kf[(it + 1) & 1];
                ldm4(nf + 0,  sKh + offa);
                ldm4(nf + 4,  sKh + offb);
                ldm4(nf + 8,  sKl + offa);
                ldm4(nf + 12, sKl + offb);
            }
            const int kq = it >> 2, ngp = it & 3;
            const uint32_t* f = kf[it & 1];
            float* a0 = sacc[4 * ngp + 0];
            float* a1 = sacc[4 * ngp + 1];
            float* a2 = sacc[4 * ngp + 2];
            float* a3 = sacc[4 * ngp + 3];
            mma16816(a0, qfh[kq], f[0], f[2]);
            mma16816(a1, qfh[kq], f[1], f[3]);
            mma16816(a2, qfh[kq], f[4], f[6]);
            mma16816(a3, qfh[kq], f[5], f[7]);
            mma16816(a0, qfh[kq], f[8], f[10]);
            mma16816(a1, qfh[kq], f[9], f[11]);
            mma16816(a2, qfh[kq], f[12], f[14]);
            mma16816(a3, qfh[kq], f[13], f[15]);
        }

        // mask + online softmax (base-2)
        const int kvalid = NTOT - kt * 128;
        if (kvalid < 128) {
#pragma unroll
            for (int nt = 0; nt < 16; nt++) {
                const int c0 = nt * 8 + 2 * tg;
                if (c0 >= kvalid)     { sacc[nt][0] = -1e30f; sacc[nt][2] = -1e30f; }
                if (c0 + 1 >= kvalid) { sacc[nt][1] = -1e30f; sacc[nt][3] = -1e30f; }
            }
        }
        float mx0 = -1e30f, mx1 = -1e30f;
#pragma unroll
        for (int nt = 0; nt < 16; nt++) {
            mx0 = fmaxf(mx0, fmaxf(sacc[nt][0], sacc[nt][1]));
            mx1 = fmaxf(mx1, fmaxf(sacc[nt][2], sacc[nt][3]));
        }
        mx0 = fmaxf(mx0, __shfl_xor_sync(0xffffffffu, mx0, 1));
        mx0 = fmaxf(mx0, __shfl_xor_sync(0xffffffffu, mx0, 2));
        mx1 = fmaxf(mx1, __shfl_xor_sync(0xffffffffu, mx1, 1));
        mx1 = fmaxf(mx1, __shfl_xor_sync(0xffffffffu, mx1, 2));
        const float mn0 = fmaxf(m0, mx0), mn1 = fmaxf(m1, mx1);
        const float cr0 = ex2f(m0 - mn0), cr1 = ex2f(m1 - mn1);
        m0 = mn0; m1 = mn1;
        float s0 = 0.f, s1 = 0.f;
#pragma unroll
        for (int nt = 0; nt < 16; nt++) {
            sacc[nt][0] = ex2f(sacc[nt][0] - mn0);
            sacc[nt][1] = ex2f(sacc[nt][1] - mn0);
            sacc[nt][2] = ex2f(sacc[nt][2] - mn1);
            sacc[nt][3] = ex2f(sacc[nt][3] - mn1);
            s0 += sacc[nt][0] + sacc[nt][1];
            s1 += sacc[nt][2] + sacc[nt][3];
        }
        s0 += __shfl_xor_sync(0xffffffffu, s0, 1);
        s0 += __shfl_xor_sync(0xffffffffu, s0, 2);
        s1 += __shfl_xor_sync(0xffffffffu, s1, 1);
        s1 += __shfl_xor_sync(0xffffffffu, s1, 2);
        l0 = l0 * cr0 + s0; l1 = l1 * cr1 + s1;
#pragma unroll
        for (int nt = 0; nt < 8; nt++) {
            oacc[nt][0] *= cr0; oacc[nt][1] *= cr0;
            oacc[nt][2] *= cr1; oacc[nt][3] *= cr1;
        }

        // ---- O += Ph*(Vh+Vl) : pipelined fragment loads (it = kc*2 + ngp) ----
        // fragment layout: [0..3]=vha [4..7]=vhb [8..11]=vla [12..15]=vlb
        uint32_t vf[2][16];
        {
            const int row0 = l15;
            const int cca0 = khalf, ccb0 = 2 + khalf;
            const uint32_t offa0 = (row0 << 7) + ((cca0 ^ (row0 & 7)) << 4);
            const uint32_t offb0 = (row0 << 7) + ((ccb0 ^ (row0 & 7)) << 4);
            ldm4t(vf[0] + 0,  sVh + offa0);
            ldm4t(vf[0] + 4,  sVh + offb0);
            ldm4t(vf[0] + 8,  sVl + offa0);
            ldm4t(vf[0] + 12, sVl + offb0);
        }
        uint32_t pah[4];
#pragma unroll
        for (int it = 0; it < 16; it++) {
            if (it + 1 < 16) {
                const int nkc = (it + 1) >> 1, nngp = (it + 1) & 1;
                const int row = nkc * 16 + l15;
                const int cca = 4 * nngp + khalf, ccb = cca + 2;
                const uint32_t offa = (row << 7) + ((cca ^ (row & 7)) << 4);
                const uint32_t offb = (row << 7) + ((ccb ^ (row & 7)) << 4);
                uint32_t* nf = vf[(it + 1) & 1];
                ldm4t(nf + 0,  sVh + offa);
                ldm4t(nf + 4,  sVh + offb);
                ldm4t(nf + 8,  sVl + offa);
                ldm4t(nf + 12, sVl + offb);
            }
            const int kc = it >> 1, ngp = it & 1;
            if (ngp == 0) {   // pack P for this kc (hi only)
                const float* t0 = sacc[2 * kc];
                const float* t1 = sacc[2 * kc + 1];
                pah[0] = pkh(t0[0], t0[1]);
                pah[1] = pkh(t0[2], t0[3]);
                pah[2] = pkh(t1[0], t1[1]);
                pah[3] = pkh(t1[2], t1[3]);
            }
            const uint32_t* f = vf[it & 1];
            float* a0 = oacc[4 * ngp + 0];
            float* a1 = oacc[4 * ngp + 1];
            float* a2 = oacc[4 * ngp + 2];
            float* a3 = oacc[4 * ngp + 3];
            mma16816(a0, pah, f[0], f[1]);
            mma16816(a1, pah, f[2], f[3]);
            mma16816(a2, pah, f[4], f[5]);
            mma16816(a3, pah, f[6], f[7]);
            mma16816(a0, pah, f[8], f[9]);
            mma16816(a1, pah, f[10], f[11]);
            mma16816(a2, pah, f[12], f[13]);
            mma16816(a3, pah, f[14], f[15]);
        }
        __syncthreads();
    }

    // normalize + write ctx as single fp16 (out-proj A side is unsplit)
    const float iv0 = 1.f / l0, iv1 = 1.f / l1;
    const int n0 = qt * 128 + w * 16 + g;
    const int n1 = n0 + 8;
#pragma unroll
    for (int nt = 0; nt < 8; nt++) {
        const int d = nt * 8 + 2 * tg;
        if (n0 < NTOT) {
            const long long idx = OFF_CTX + ((long long)(b * NTOT + n0)) * HIDDEN + h * HD + d;
            *(ushort2*)(g_bh + idx) = make_ushort2(h16(oacc[nt][0] * iv0),
                                                   h16(oacc[nt][1] * iv0));
        }
        if (n1 < NTOT) {
            const long long idx = OFF_CTX + ((long long)(b * NTOT + n1)) * HIDDEN + h * HD + d;
            *(ushort2*)(g_bh + idx) = make_ushort2(h16(oacc[nt][2] * iv1),
                                                   h16(oacc[nt][3] * iv1));
        }
    }
}

// ---------------- host launcher ----------------
extern "C" void kernel_launch(void* const* d_in, const int* in_sizes, int n_in,
                              void* d_out, int out_size)
{
    (void)out_size;
    const float* video = nullptr;
    const float* action = nullptr;
    const float* wb[16];
    int wi = 0;
    for (int i = 0; i < n_in; i++) {
        const int sz = in_sizes[i];
        if (sz == BSZ * NVID * HIDDEN)       video  = (const float*)d_in[i];
        else if (sz == BSZ * NACT * HIDDEN)  action = (const float*)d_in[i];
        else if (wi < 16)                    wb[wi++] = (const float*)d_in[i];
    }
    float* out = (float*)d_out;

    cudaFuncSetAttribute(gemm_qkv_mma, cudaFuncAttributeMaxDynamicSharedMemorySize, GT_SMEM);
    cudaFuncSetAttribute(gemm_out_mma, cudaFuncAttributeMaxDynamicSharedMemorySize, GT_SMEM);
    cudaFuncSetAttribute(attn_mma, cudaFuncAttributeMaxDynamicSharedMemorySize, AT_SMEM);

    // split inputs + weights into fp16 hi/lo
    cvt_all<<<dim3(1024, 10), 256>>>(video, action, wb[0], wb[2], wb[4], wb[6],
                                     wb[8], wb[10], wb[12], wb[14]);

    // QKV projections (rope + scale + split fused in epilogue), 512 thr/CTA
    gemm_qkv_mma<<<dim3(8, 33, 3), 512, GT_SMEM>>>(wb[1], wb[3], wb[5],
                                                   wb[7], wb[9], wb[11]);

    // attention on tensor cores (fp16 2-term)
    attn_mma<<<dim3(17, 32), 256, AT_SMEM>>>();

    // output projection, 512 thr/CTA
    gemm_out_mma<<<dim3(8, 17, 2), 512, GT_SMEM>>>(wb[13], wb[15], out);
}

// round 10
// speedup vs baseline: 1.4895x; 1.0712x over previous
#include <cuda_runtime.h>
#include <cuda_fp16.h>
#include <cstdint>

#define HIDDEN 1024
#define HEADS 16
#define HD 64
#define NVID 2048
#define NACT 16
#define NTOT 2064
#define BSZ 2
#define BH (BSZ*HEADS)
// q pre-scale: ATT_SCALE * log2(e), so softmax uses exp2
#define QSC 0.18033688011112042f

#define WSZ 1048576LL
#define OFF_VIDEO 0LL
#define OFF_ACTION 4194304LL
#define OFF_W 4227072LL
#define OFF_CTX (OFF_W + 8LL * WSZ)
#define BF_TOTAL (OFF_CTX + 4227072LL)

// ---------------- scratch (device globals; no allocation allowed) ----------------
__device__ unsigned short g_bh[BF_TOTAL];    // fp16 hi: inputs, weights, ctx
__device__ unsigned short g_bl[BF_TOTAL];    // fp16 lo (weights only)
__device__ unsigned short g_qh[BH * NTOT * HD];
__device__ unsigned short g_kh[BH * NTOT * HD], g_kl[BH * NTOT * HD];
__device__ unsigned short g_vh[BH * NTOT * HD], g_vl[BH * NTOT * HD];

// ---------------- helpers ----------------
__device__ __forceinline__ void cpa16z(uint32_t dst, const void* src, int bytes) {
    asm volatile("cp.async.cg.shared.global [%0], [%1], 16, %2;"
                 :: "r"(dst), "l"(src), "r"(bytes) : "memory");
}
__device__ __forceinline__ void cp_commit() {
    asm volatile("cp.async.commit_group;" ::: "memory");
}
__device__ __forceinline__ uint32_t smem_u32(const void* p) {
    return (uint32_t)__cvta_generic_to_shared(p);
}
__device__ __forceinline__ void ldm4(uint32_t* r, uint32_t addr) {
    asm volatile("ldmatrix.sync.aligned.m8n8.x4.shared.b16 {%0,%1,%2,%3}, [%4];"
                 : "=r"(r[0]), "=r"(r[1]), "=r"(r[2]), "=r"(r[3]) : "r"(addr));
}
__device__ __forceinline__ void ldm4t(uint32_t* r, uint32_t addr) {
    asm volatile("ldmatrix.sync.aligned.m8n8.x4.trans.shared.b16 {%0,%1,%2,%3}, [%4];"
                 : "=r"(r[0]), "=r"(r[1]), "=r"(r[2]), "=r"(r[3]) : "r"(addr));
}
__device__ __forceinline__ void mma16816(float* c, const uint32_t* a,
                                         uint32_t b0, uint32_t b1) {
    asm volatile("mma.sync.aligned.m16n8k16.row.col.f32.f16.f16.f32 "
                 "{%0,%1,%2,%3}, {%4,%5,%6,%7}, {%8,%9}, {%0,%1,%2,%3};"
                 : "+f"(c[0]), "+f"(c[1]), "+f"(c[2]), "+f"(c[3])
                 : "r"(a[0]), "r"(a[1]), "r"(a[2]), "r"(a[3]), "r"(b0), "r"(b1));
}
__device__ __forceinline__ void hsplit(float x, unsigned short& h, unsigned short& l) {
    __half hb = __float2half_rn(x);
    h = __half_as_ushort(hb);
    l = __half_as_ushort(__float2half_rn(x - __half2float(hb)));
}
__device__ __forceinline__ unsigned short h16(float x) {
    return __half_as_ushort(__float2half_rn(x));
}
__device__ __forceinline__ uint32_t pkh(float lo, float hi) {
    uint32_t r;
    asm("cvt.rn.f16x2.f32 %0, %1, %2;" : "=r"(r) : "f"(hi), "f"(lo));
    return r;
}
__device__ __forceinline__ float ex2f(float x) {
    float y; asm("ex2.approx.ftz.f32 %0, %1;" : "=f"(y) : "f"(x)); return y;
}

// ---------------- fp32 -> fp16 hi/lo split (inputs + weights) ----------------
__global__ void cvt_all(const float* v, const float* a,
                        const float* w0, const float* w1, const float* w2,
                        const float* w3, const float* w4, const float* w5,
                        const float* w6, const float* w7)
{
    const float* srcs[10] = { v, a, w0, w1, w2, w3, w4, w5, w6, w7 };
    const long long offs[10] = { OFF_VIDEO, OFF_ACTION,
        OFF_W + 0 * WSZ, OFF_W + 1 * WSZ, OFF_W + 2 * WSZ, OFF_W + 3 * WSZ,
        OFF_W + 4 * WSZ, OFF_W + 5 * WSZ, OFF_W + 6 * WSZ, OFF_W + 7 * WSZ };
    const int cnts[10] = { 4194304, 32768, 1048576, 1048576, 1048576, 1048576,
                           1048576, 1048576, 1048576, 1048576 };
    const int z = blockIdx.y;
    const float4* src = (const float4*)srcs[z];
    ushort4* hi = (ushort4*)(g_bh + offs[z]);
    ushort4* lo = (ushort4*)(g_bl + offs[z]);
    const bool wlo = (z >= 2);
    const int n4 = cnts[z] >> 2;
    for (int i = blockIdx.x * blockDim.x + threadIdx.x; i < n4;
         i += gridDim.x * blockDim.x) {
        const float4 x = src[i];
        ushort4 h, l;
        hsplit(x.x, h.x, l.x); hsplit(x.y, h.y, l.y);
        hsplit(x.z, h.z, l.z); hsplit(x.w, h.w, l.w);
        hi[i] = h;
        if (wlo) lo[i] = l;
    }
}

// ================= mma.sync fp16x2 GEMM (projections), 512 threads =================
#define GT_TILE 16384
#define GT_BUF  (3 * GT_TILE)
#define GT_SMEM (2 * GT_BUF)          // 96 KB

__device__ __forceinline__ void gstage(const unsigned short* Ah,
                                       int M, int rowTile,
                                       const unsigned short* Wh, const unsigned short* Wl,
                                       int colTile, int k0, uint32_t bufb, int tid)
{
#pragma unroll
    for (int i = 0; i < 6; i++) {
        const int tile = i >> 1;
        const int t = ((i & 1) << 9) + tid;
        const int row = t >> 3, c = t & 7;
        const uint32_t dst = bufb + tile * GT_TILE + (row << 7) + ((c ^ (row & 7)) << 4);
        if (tile == 0) {
            const int m = rowTile + row;
            const int mm = (m < M) ? m : 0;
            const unsigned short* s = Ah + (long long)mm * 1024 + k0 + c * 8;
            cpa16z(dst, s, (m < M) ? 16 : 0);
        } else {
            const unsigned short* s = (tile == 1 ? Wh : Wl) +
                                      (long long)(colTile + row) * 1024 + k0 + c * 8;
            cpa16z(dst, s, 16);
        }
    }
}

// MODE 0: fp32 out[m*1024+n];  MODE 1: video qkv split+rope;  MODE 2: action qkv split
template <int MODE>
__device__ __forceinline__ void gemm_body(const unsigned short* Ah,
                                          int M, int rowTile,
                                          const unsigned short* Wh, const unsigned short* Wl,
                                          int colTile, const float* bias,
                                          float* __restrict__ outf,
                                          unsigned short* __restrict__ oh,
                                          unsigned short* __restrict__ ol, int rk)
{
    extern __shared__ char dsmem[];
    const uint32_t sbase = smem_u32(dsmem);
    const int tid = threadIdx.x;
    const int lane = tid & 31, wid = tid >> 5;
    const int warp_m = wid >> 2, warp_n = wid & 3;

    float acc[2][4][4];
#pragma unroll
    for (int a = 0; a < 2; a++)
#pragma unroll
        for (int b = 0; b < 4; b++)
#pragma unroll
            for (int c = 0; c < 4; c++) acc[a][b][c] = 0.f;

    int rA[2], rW[2];
#pragma unroll
    for (int mt = 0; mt < 2; mt++) rA[mt] = warp_m * 32 + mt * 16 + (lane & 15);
#pragma unroll
    for (int nt2 = 0; nt2 < 2; nt2++) rW[nt2] = warp_n * 32 + nt2 * 16 + (lane & 15);
    const int khalf = lane >> 4;

    gstage(Ah, M, rowTile, Wh, Wl, colTile, 0, sbase, tid);
    cp_commit();

    for (int c = 0; c < 16; c++) {
        if (c + 1 < 16) {
            gstage(Ah, M, rowTile, Wh, Wl, colTile, (c + 1) * 64,
                   sbase + ((c + 1) & 1) * GT_BUF, tid);
            cp_commit();
            asm volatile("cp.async.wait_group 1;" ::: "memory");
        } else {
            asm volatile("cp.async.wait_group 0;" ::: "memory");
        }
        __syncthreads();

        const uint32_t bufb = sbase + (c & 1) * GT_BUF;
        const uint32_t sAh = bufb;
        const uint32_t sWh = bufb + GT_TILE, sWl = bufb + 2 * GT_TILE;

#pragma unroll
        for (int kq = 0; kq < 4; kq++) {
            const int kp = 2 * kq + khalf;
            uint32_t ah[2][4], wh[2][4], wl[2][4];
#pragma unroll
            for (int mt = 0; mt < 2; mt++) {
                const uint32_t off = (rA[mt] << 7) + ((kp ^ (rA[mt] & 7)) << 4);
                ldm4(ah[mt], sAh + off);
            }
#pragma unroll
            for (int nt2 = 0; nt2 < 2; nt2++) {
                const uint32_t off = (rW[nt2] << 7) + ((kp ^ (rW[nt2] & 7)) << 4);
                ldm4(wh[nt2], sWh + off);
                ldm4(wl[nt2], sWl + off);
            }
#pragma unroll
            for (int term = 0; term < 2; term++) {
#pragma unroll
                for (int mt = 0; mt < 2; mt++) {
#pragma unroll
                    for (int nt = 0; nt < 4; nt++) {
                        const uint32_t* wfrag = (term == 1) ? wl[nt >> 1] : wh[nt >> 1];
                        mma16816(acc[mt][nt], ah[mt],
                                 wfrag[nt & 1], wfrag[(nt & 1) + 2]);
                    }
                }
            }
        }
        __syncthreads();
    }

    const int g = lane >> 2, tg = lane & 3;
#pragma unroll
    for (int mt = 0; mt < 2; mt++) {
#pragma unroll
        for (int nt = 0; nt < 4; nt++) {
            const int n0 = colTile + warp_n * 32 + nt * 8 + tg * 2;
            const float2 bv = *(const float2*)(bias + n0);
#pragma unroll
            for (int hf = 0; hf < 2; hf++) {
                const int m = rowTile + warp_m * 32 + mt * 16 + g + hf * 8;
                if (m >= M) continue;
                float v0 = acc[mt][nt][hf * 2 + 0] + bv.x;
                float v1 = acc[mt][nt][hf * 2 + 1] + bv.y;
                if (MODE == 0) {
                    float2 o; o.x = v0; o.y = v1;
                    *(float2*)(outf + (long long)m * 1024 + n0) = o;
                } else {
                    int b_, nn;
                    if (MODE == 1) { b_ = m >> 11; nn = m & 2047; }
                    else           { b_ = m >> 4;  nn = NVID + (m & 15); }
                    const int hh = n0 >> 6, d = n0 & 63;
                    if (MODE == 1 && rk && d < 60) {
                        const int seg = d / 20, jj = (d - seg * 20) >> 1;
                        const int pos = (seg == 0) ? (nn >> 8)
                                      : (seg == 1) ? ((nn >> 4) & 15) : (nn & 15);
                        const float omega = ex2f(-(float)jj * 1.3287712379549449f);
                        float sn, cs;
                        sincosf((float)pos * omega, &sn, &cs);
                        const float x1 = v0 * cs - v1 * sn;
                        const float x2 = v1 * cs + v0 * sn;
                        v0 = x1; v1 = x2;
                    }
                    const long long idx = (((long long)(b_ * HEADS + hh)) * NTOT + nn) * HD + d;
                    if (rk == 1) {
                        v0 *= QSC; v1 *= QSC;
                        *(ushort2*)(oh + idx) = make_ushort2(h16(v0), h16(v1));
                    } else {
                        unsigned short h0, l0_, h1, l1_;
                        hsplit(v0, h0, l0_); hsplit(v1, h1, l1_);
                        *(ushort2*)(oh + idx) = make_ushort2(h0, h1);
                        *(ushort2*)(ol + idx) = make_ushort2(l0_, l1_);
                    }
                }
            }
        }
    }
}

// grid (8, 33, 3): z = {q,k,v}; by<32 video rows; by==32 action rows
__global__ __launch_bounds__(512, 1)
void gemm_qkv_mma(const float* bq, const float* bk, const float* bv,
                  const float* bqa, const float* bka, const float* bva)
{
    const int z = blockIdx.z;
    const bool act = (blockIdx.y == 32);
    const unsigned short* Ah = g_bh + (act ? OFF_ACTION : OFF_VIDEO);
    const int M = act ? (BSZ * NACT) : (BSZ * NVID);
    const int rowTile = act ? 0 : blockIdx.y * 128;
    const int colTile = blockIdx.x * 128;
    const int widx = z + (act ? 3 : 0);
    const unsigned short* Wh = g_bh + OFF_W + widx * WSZ;
    const unsigned short* Wl = g_bl + OFF_W + widx * WSZ;
    const float* bias = act ? (z == 0 ? bqa : (z == 1 ? bka : bva))
                            : (z == 0 ? bq : (z == 1 ? bk : bv));
    unsigned short *oh, *ol;
    int rk;
    if (z == 0)      { oh = g_qh; ol = nullptr; rk = 1; }
    else if (z == 1) { oh = g_kh; ol = g_kl; rk = 2; }
    else             { oh = g_vh; ol = g_vl; rk = 0; }
    if (act) gemm_body<2>(Ah, M, rowTile, Wh, Wl, colTile, bias, nullptr, oh, ol, rk);
    else     gemm_body<1>(Ah, M, rowTile, Wh, Wl, colTile, bias, nullptr, oh, ol, rk);
}

// grid (8, 17, 2): z = batch; by<16 video rows; by==16 action rows
__global__ __launch_bounds__(512, 1)
void gemm_out_mma(const float* bp, const float* bpa, float* __restrict__ dout)
{
    const int z = blockIdx.z;
    const bool act = (blockIdx.y == 16);
    const long long aoff = OFF_CTX + (long long)z * NTOT * HIDDEN +
                           (act ? (long long)NVID * HIDDEN : 0);
    const unsigned short* Ah = g_bh + aoff;
    const int M = act ? NACT : NVID;
    const int rowTile = act ? 0 : blockIdx.y * 128;
    const int colTile = blockIdx.x * 128;
    const int widx = act ? 7 : 6;
    const unsigned short* Wh = g_bh + OFF_W + widx * WSZ;
    const unsigned short* Wl = g_bl + OFF_W + widx * WSZ;
    const float* bias = act ? bpa : bp;
    float* C = act ? (dout + (long long)BSZ * NVID * HIDDEN + (long long)z * NACT * HIDDEN)
                   : (dout + (long long)z * NVID * HIDDEN);
    gemm_body<0>(Ah, M, rowTile, Wh, Wl, colTile, bias, C, nullptr, nullptr, 0);
}

// ================= flash attention: 64 q-rows, 4 warps, 3 CTAs/SM =================
// smem: Q 8K + 4 rotating 16K K/V buffers = 72 KB -> 3 CTAs/SM.
// K(kt) -> buf[(kt&1)*2], V(kt) -> buf[(kt&1)*2+1]; prefetch distance 1.5 tiles.
#define AT_QOFF 0
#define AT_BUF(i) (8192 + (i) * 16384)
#define AT_SMEM (8192 + 4 * 16384)    // 73728

__device__ __forceinline__ void stage_k64(long long base, int kt, uint32_t bufb, int tid) {
#pragma unroll
    for (int i = 0; i < 8; i++) {
        const int arr = i >> 2;                  // 0 = hi, 1 = lo
        const int t = ((i & 3) << 7) + tid;      // 0..511
        const int row = t >> 3, c = t & 7;
        const int key = kt * 64 + row;
        const uint32_t dst = bufb + arr * 8192 + (row << 7) + ((c ^ (row & 7)) << 4);
        const unsigned short* s = (arr == 0 ? g_kh : g_kl) +
            base + (long long)(key < NTOT ? key : 0) * HD + c * 8;
        cpa16z(dst, s, (key < NTOT) ? 16 : 0);
    }
}
__device__ __forceinline__ void stage_v64(long long base, int kt, uint32_t bufb, int tid) {
#pragma unroll
    for (int i = 0; i < 8; i++) {
        const int arr = i >> 2;
        const int t = ((i & 3) << 7) + tid;
        const int row = t >> 3, c = t & 7;
        const int key = kt * 64 + row;
        const uint32_t dst = bufb + arr * 8192 + (row << 7) + ((c ^ (row & 7)) << 4);
        const unsigned short* s = (arr == 0 ? g_vh : g_vl) +
            base + (long long)(key < NTOT ? key : 0) * HD + c * 8;
        cpa16z(dst, s, (key < NTOT) ? 16 : 0);
    }
}

__global__ __launch_bounds__(128, 3)
void attn_mma()
{
    extern __shared__ char dsm[];
    const uint32_t sb = smem_u32(dsm);
    const int tid = threadIdx.x, lane = tid & 31, w = tid >> 5;   // 4 warps
    const int qt = blockIdx.x, bh = blockIdx.y;
    const int b = bh >> 4, h = bh & 15;
    const long long base = (long long)bh * NTOT * HD;
    const int g = lane >> 2, tg = lane & 3;
    const int khalf = lane >> 4, l15 = lane & 15;

    // prologue: G0 = {Q, K0}, G1 = {V0}, G2 = {K1}
#pragma unroll
    for (int i = 0; i < 4; i++) {
        const int t = (i << 7) + tid;
        const int row = t >> 3, c = t & 7;
        const int n = qt * 64 + row;
        const uint32_t dst = sb + AT_QOFF + (row << 7) + ((c ^ (row & 7)) << 4);
        const unsigned short* src = g_qh + base + (long long)(n < NTOT ? n : 0) * HD + c * 8;
        cpa16z(dst, src, (n < NTOT) ? 16 : 0);
    }
    stage_k64(base, 0, sb + AT_BUF(0), tid);
    cp_commit();
    stage_v64(base, 0, sb + AT_BUF(1), tid);
    cp_commit();
    stage_k64(base, 1, sb + AT_BUF(2), tid);
    cp_commit();

    float oacc[8][4];
#pragma unroll
    for (int i = 0; i < 8; i++)
#pragma unroll
        for (int j = 0; j < 4; j++) oacc[i][j] = 0.f;
    float m0 = -1e30f, m1 = -1e30f, l0 = 0.f, l1 = 0.f;
    uint32_t qfh[4][4];

    const int NKT = 33;   // 33 * 64 = 2112 >= 2064
    for (int kt = 0; kt < NKT; kt++) {
        // K(kt) ready (pending after: V(kt), K(kt+1))
        asm volatile("cp.async.wait_group 2;" ::: "memory");
        __syncthreads();

        if (kt == 0) {   // Q fragments (once)
            const int row = w * 16 + l15;
#pragma unroll
            for (int kq = 0; kq < 4; kq++) {
                const int kp = 2 * kq + khalf;
                const uint32_t off = (row << 7) + ((kp ^ (row & 7)) << 4);
                ldm4(qfh[kq], sb + AT_QOFF + off);
            }
        }

        // prefetch V(kt+1) into V(kt-1)'s slot (free: all warps past PV(kt-1))
        if (kt + 1 < NKT)
            stage_v64(base, kt + 1, sb + AT_BUF(((kt + 1) & 1) * 2 + 1), tid);
        cp_commit();   // always commit (possibly empty) to keep group counts aligned

        const uint32_t sKh = sb + AT_BUF((kt & 1) * 2);
        const uint32_t sKl = sKh + 8192;

        float sacc[8][4];
#pragma unroll
        for (int i = 0; i < 8; i++)
#pragma unroll
            for (int j = 0; j < 4; j++) sacc[i][j] = 0.f;

        // S = Qh*(Kh+Kl), 64 keys
#pragma unroll
        for (int kq = 0; kq < 4; kq++) {
            const int kp = 2 * kq + khalf;
#pragma unroll
            for (int ng = 0; ng < 4; ng++) {
                const int row = ng * 16 + l15;
                const uint32_t off = (row << 7) + ((kp ^ (row & 7)) << 4);
                uint32_t kh4[4], kl4[4];
                ldm4(kh4, sKh + off);
                ldm4(kl4, sKl + off);
                float* a0 = sacc[2 * ng + 0];
                float* a1 = sacc[2 * ng + 1];
                mma16816(a0, qfh[kq], kh4[0], kh4[2]);
                mma16816(a1, qfh[kq], kh4[1], kh4[3]);
                mma16816(a0, qfh[kq], kl4[0], kl4[2]);
                mma16816(a1, qfh[kq], kl4[1], kl4[3]);
            }
        }

        // mask + online softmax (base-2)
        const int kvalid = NTOT - kt * 64;
        if (kvalid < 64) {
#pragma unroll
            for (int nt = 0; nt < 8; nt++) {
                const int c0 = nt * 8 + 2 * tg;
                if (c0 >= kvalid)     { sacc[nt][0] = -1e30f; sacc[nt][2] = -1e30f; }
                if (c0 + 1 >= kvalid) { sacc[nt][1] = -1e30f; sacc[nt][3] = -1e30f; }
            }
        }
        float mx0 = -1e30f, mx1 = -1e30f;
#pragma unroll
        for (int nt = 0; nt < 8; nt++) {
            mx0 = fmaxf(mx0, fmaxf(sacc[nt][0], sacc[nt][1]));
            mx1 = fmaxf(mx1, fmaxf(sacc[nt][2], sacc[nt][3]));
        }
        mx0 = fmaxf(mx0, __shfl_xor_sync(0xffffffffu, mx0, 1));
        mx0 = fmaxf(mx0, __shfl_xor_sync(0xffffffffu, mx0, 2));
        mx1 = fmaxf(mx1, __shfl_xor_sync(0xffffffffu, mx1, 1));
        mx1 = fmaxf(mx1, __shfl_xor_sync(0xffffffffu, mx1, 2));
        const float mn0 = fmaxf(m0, mx0), mn1 = fmaxf(m1, mx1);
        const float cr0 = ex2f(m0 - mn0), cr1 = ex2f(m1 - mn1);
        m0 = mn0; m1 = mn1;
        float s0 = 0.f, s1 = 0.f;
#pragma unroll
        for (int nt = 0; nt < 8; nt++) {
            sacc[nt][0] = ex2f(sacc[nt][0] - mn0);
            sacc[nt][1] = ex2f(sacc[nt][1] - mn0);
            sacc[nt][2] = ex2f(sacc[nt][2] - mn1);
            sacc[nt][3] = ex2f(sacc[nt][3] - mn1);
            s0 += sacc[nt][0] + sacc[nt][1];
            s1 += sacc[nt][2] + sacc[nt][3];
        }
        s0 += __shfl_xor_sync(0xffffffffu, s0, 1);
        s0 += __shfl_xor_sync(0xffffffffu, s0, 2);
        s1 += __shfl_xor_sync(0xffffffffu, s1, 1);
        s1 += __shfl_xor_sync(0xffffffffu, s1, 2);
        l0 = l0 * cr0 + s0; l1 = l1 * cr1 + s1;
#pragma unroll
        for (int nt = 0; nt < 8; nt++) {
            oacc[nt][0] *= cr0; oacc[nt][1] *= cr0;
            oacc[nt][2] *= cr1; oacc[nt][3] *= cr1;
        }

        // V(kt) ready (pending after: K(kt+1), V(kt+1))
        asm volatile("cp.async.wait_group 2;" ::: "memory");
        __syncthreads();   // V visible; all warps done reading K(kt)

        // prefetch K(kt+2) into K(kt)'s slot
        if (kt + 2 < NKT)
            stage_k64(base, kt + 2, sb + AT_BUF((kt & 1) * 2), tid);
        cp_commit();

        const uint32_t sVh = sb + AT_BUF((kt & 1) * 2 + 1);
        const uint32_t sVl = sVh + 8192;

        // O += Ph*(Vh+Vl)
#pragma unroll
        for (int kc = 0; kc < 4; kc++) {
            uint32_t pah[4];
            const float* t0 = sacc[2 * kc];
            const float* t1 = sacc[2 * kc + 1];
            pah[0] = pkh(t0[0], t0[1]);
            pah[1] = pkh(t0[2], t0[3]);
            pah[2] = pkh(t1[0], t1[1]);
            pah[3] = pkh(t1[2], t1[3]);
            const int row = kc * 16 + l15;
#pragma unroll
            for (int ng = 0; ng < 4; ng++) {
                const int cc = 2 * ng + khalf;
                const uint32_t off = (row << 7) + ((cc ^ (row & 7)) << 4);
                uint32_t vh4[4], vl4[4];
                ldm4t(vh4, sVh + off);
                ldm4t(vl4, sVl + off);
                float* a0 = oacc[2 * ng + 0];
                float* a1 = oacc[2 * ng + 1];
                mma16816(a0, pah, vh4[0], vh4[1]);
                mma16816(a1, pah, vh4[2], vh4[3]);
                mma16816(a0, pah, vl4[0], vl4[1]);
                mma16816(a1, pah, vl4[2], vl4[3]);
            }
        }
    }

    // normalize + write ctx as fp16 (out-proj A side)
    const float iv0 = 1.f / l0, iv1 = 1.f / l1;
    const int n0 = qt * 64 + w * 16 + g;
    const int n1 = n0 + 8;
#pragma unroll
    for (int nt = 0; nt < 8; nt++) {
        const int d = nt * 8 + 2 * tg;
        if (n0 < NTOT) {
            const long long idx = OFF_CTX + ((long long)(b * NTOT + n0)) * HIDDEN + h * HD + d;
            *(ushort2*)(g_bh + idx) = make_ushort2(h16(oacc[nt][0] * iv0),
                                                   h16(oacc[nt][1] * iv0));
        }
        if (n1 < NTOT) {
            const long long idx = OFF_CTX + ((long long)(b * NTOT + n1)) * HIDDEN + h * HD + d;
            *(ushort2*)(g_bh + idx) = make_ushort2(h16(oacc[nt][2] * iv1),
                                                   h16(oacc[nt][3] * iv1));
        }
    }
}

// ---------------- host launcher ----------------
extern "C" void kernel_launch(void* const* d_in, const int* in_sizes, int n_in,
                              void* d_out, int out_size)
{
    (void)out_size;
    const float* video = nullptr;
    const float* action = nullptr;
    const float* wb[16];
    int wi = 0;
    for (int i = 0; i < n_in; i++) {
        const int sz = in_sizes[i];
        if (sz == BSZ * NVID * HIDDEN)       video  = (const float*)d_in[i];
        else if (sz == BSZ * NACT * HIDDEN)  action = (const float*)d_in[i];
        else if (wi < 16)                    wb[wi++] = (const float*)d_in[i];
    }
    float* out = (float*)d_out;

    cudaFuncSetAttribute(gemm_qkv_mma, cudaFuncAttributeMaxDynamicSharedMemorySize, GT_SMEM);
    cudaFuncSetAttribute(gemm_out_mma, cudaFuncAttributeMaxDynamicSharedMemorySize, GT_SMEM);
    cudaFuncSetAttribute(attn_mma, cudaFuncAttributeMaxDynamicSharedMemorySize, AT_SMEM);

    // split inputs + weights into fp16 hi/lo
    cvt_all<<<dim3(1024, 10), 256>>>(video, action, wb[0], wb[2], wb[4], wb[6],
                                     wb[8], wb[10], wb[12], wb[14]);

    // QKV projections (rope + scale + split fused in epilogue)
    gemm_qkv_mma<<<dim3(8, 33, 3), 512, GT_SMEM>>>(wb[1], wb[3], wb[5],
                                                   wb[7], wb[9], wb[11]);

    // attention: 64-q-row CTAs, 3 CTAs/SM
    attn_mma<<<dim3(33, 32), 128, AT_SMEM>>>();

    // output projection
    gemm_out_mma<<<dim3(8, 17, 2), 512, GT_SMEM>>>(wb[13], wb[15], out);
}

// round 11
// speedup vs baseline: 1.7743x; 1.1912x over previous
#include <cuda_runtime.h>
#include <cuda_fp16.h>
#include <cstdint>

#define HIDDEN 1024
#define HEADS 16
#define HD 64
#define NVID 2048
#define NACT 16
#define NTOT 2064
#define BSZ 2
#define BH (BSZ*HEADS)
// q pre-scale: ATT_SCALE * log2(e), so softmax uses exp2
#define QSC 0.18033688011112042f

#define WSZ 1048576LL
#define OFF_VIDEO 0LL
#define OFF_ACTION 4194304LL
#define OFF_W 4227072LL
#define OFF_CTX (OFF_W + 8LL * WSZ)
#define BF_TOTAL (OFF_CTX + 4227072LL)

// ---------------- scratch (device globals; no allocation allowed) ----------------
__device__ unsigned short g_bh[BF_TOTAL];    // fp16 hi: inputs, weights, ctx
__device__ unsigned short g_bl[BF_TOTAL];    // fp16 lo (weights only)
__device__ unsigned short g_qh[BH * NTOT * HD];
__device__ unsigned short g_kh[BH * NTOT * HD];
__device__ unsigned short g_vh[BH * NTOT * HD];

// ---------------- helpers ----------------
__device__ __forceinline__ void cpa16z(uint32_t dst, const void* src, int bytes) {
    asm volatile("cp.async.cg.shared.global [%0], [%1], 16, %2;"
                 :: "r"(dst), "l"(src), "r"(bytes) : "memory");
}
__device__ __forceinline__ void cp_commit() {
    asm volatile("cp.async.commit_group;" ::: "memory");
}
__device__ __forceinline__ uint32_t smem_u32(const void* p) {
    return (uint32_t)__cvta_generic_to_shared(p);
}
__device__ __forceinline__ void ldm4(uint32_t* r, uint32_t addr) {
    asm volatile("ldmatrix.sync.aligned.m8n8.x4.shared.b16 {%0,%1,%2,%3}, [%4];"
                 : "=r"(r[0]), "=r"(r[1]), "=r"(r[2]), "=r"(r[3]) : "r"(addr));
}
__device__ __forceinline__ void ldm4t(uint32_t* r, uint32_t addr) {
    asm volatile("ldmatrix.sync.aligned.m8n8.x4.trans.shared.b16 {%0,%1,%2,%3}, [%4];"
                 : "=r"(r[0]), "=r"(r[1]), "=r"(r[2]), "=r"(r[3]) : "r"(addr));
}
// fp32-accum HMMA
__device__ __forceinline__ void mma16816(float* c, const uint32_t* a,
                                         uint32_t b0, uint32_t b1) {
    asm volatile("mma.sync.aligned.m16n8k16.row.col.f32.f16.f16.f32 "
                 "{%0,%1,%2,%3}, {%4,%5,%6,%7}, {%8,%9}, {%0,%1,%2,%3};"
                 : "+f"(c[0]), "+f"(c[1]), "+f"(c[2]), "+f"(c[3])
                 : "r"(a[0]), "r"(a[1]), "r"(a[2]), "r"(a[3]), "r"(b0), "r"(b1));
}
// fp16-accum HMMA (for tiny correction terms)
__device__ __forceinline__ void mma16816h(uint32_t* c, const uint32_t* a,
                                          uint32_t b0, uint32_t b1) {
    asm volatile("mma.sync.aligned.m16n8k16.row.col.f16.f16.f16.f16 "
                 "{%0,%1}, {%2,%3,%4,%5}, {%6,%7}, {%0,%1};"
                 : "+r"(c[0]), "+r"(c[1])
                 : "r"(a[0]), "r"(a[1]), "r"(a[2]), "r"(a[3]), "r"(b0), "r"(b1));
}
__device__ __forceinline__ void hsplit(float x, unsigned short& h, unsigned short& l) {
    __half hb = __float2half_rn(x);
    h = __half_as_ushort(hb);
    l = __half_as_ushort(__float2half_rn(x - __half2float(hb)));
}
__device__ __forceinline__ unsigned short h16(float x) {
    return __half_as_ushort(__float2half_rn(x));
}
__device__ __forceinline__ uint32_t pkh(float lo, float hi) {
    uint32_t r;
    asm("cvt.rn.f16x2.f32 %0, %1, %2;" : "=r"(r) : "f"(hi), "f"(lo));
    return r;
}
__device__ __forceinline__ float ex2f(float x) {
    float y; asm("ex2.approx.ftz.f32 %0, %1;" : "=f"(y) : "f"(x)); return y;
}

// ---------------- fp32 -> fp16 hi/lo split (inputs + weights) ----------------
__global__ void cvt_all(const float* v, const float* a,
                        const float* w0, const float* w1, const float* w2,
                        const float* w3, const float* w4, const float* w5,
                        const float* w6, const float* w7)
{
    const float* srcs[10] = { v, a, w0, w1, w2, w3, w4, w5, w6, w7 };
    const long long offs[10] = { OFF_VIDEO, OFF_ACTION,
        OFF_W + 0 * WSZ, OFF_W + 1 * WSZ, OFF_W + 2 * WSZ, OFF_W + 3 * WSZ,
        OFF_W + 4 * WSZ, OFF_W + 5 * WSZ, OFF_W + 6 * WSZ, OFF_W + 7 * WSZ };
    const int cnts[10] = { 4194304, 32768, 1048576, 1048576, 1048576, 1048576,
                           1048576, 1048576, 1048576, 1048576 };
    const int z = blockIdx.y;
    const float4* src = (const float4*)srcs[z];
    ushort4* hi = (ushort4*)(g_bh + offs[z]);
    ushort4* lo = (ushort4*)(g_bl + offs[z]);
    const bool wlo = (z >= 2);
    const int n4 = cnts[z] >> 2;
    for (int i = blockIdx.x * blockDim.x + threadIdx.x; i < n4;
         i += gridDim.x * blockDim.x) {
        const float4 x = src[i];
        ushort4 h, l;
        hsplit(x.x, h.x, l.x); hsplit(x.y, h.y, l.y);
        hsplit(x.z, h.z, l.z); hsplit(x.w, h.w, l.w);
        hi[i] = h;
        if (wlo) lo[i] = l;
    }
}

// ================= mma.sync fp16 GEMM (projections), 512 threads =================
// C = Ah*Wh (fp32 accum) + Ah*Wl (fp16 accum; correction ~2^-11 of main)
#define GT_TILE 16384
#define GT_BUF  (3 * GT_TILE)
#define GT_SMEM (2 * GT_BUF)          // 96 KB

__device__ __forceinline__ void gstage(const unsigned short* Ah,
                                       int M, int rowTile,
                                       const unsigned short* Wh, const unsigned short* Wl,
                                       int colTile, int k0, uint32_t bufb, int tid)
{
#pragma unroll
    for (int i = 0; i < 6; i++) {
        const int tile = i >> 1;
        const int t = ((i & 1) << 9) + tid;
        const int row = t >> 3, c = t & 7;
        const uint32_t dst = bufb + tile * GT_TILE + (row << 7) + ((c ^ (row & 7)) << 4);
        if (tile == 0) {
            const int m = rowTile + row;
            const int mm = (m < M) ? m : 0;
            const unsigned short* s = Ah + (long long)mm * 1024 + k0 + c * 8;
            cpa16z(dst, s, (m < M) ? 16 : 0);
        } else {
            const unsigned short* s = (tile == 1 ? Wh : Wl) +
                                      (long long)(colTile + row) * 1024 + k0 + c * 8;
            cpa16z(dst, s, 16);
        }
    }
}

// MODE 0: fp32 out[m*1024+n];  MODE 1: video qkv + rope;  MODE 2: action qkv
template <int MODE>
__device__ __forceinline__ void gemm_body(const unsigned short* Ah,
                                          int M, int rowTile,
                                          const unsigned short* Wh, const unsigned short* Wl,
                                          int colTile, const float* bias,
                                          float* __restrict__ outf,
                                          unsigned short* __restrict__ oh, int rk)
{
    extern __shared__ char dsmem[];
    const uint32_t sbase = smem_u32(dsmem);
    const int tid = threadIdx.x;
    const int lane = tid & 31, wid = tid >> 5;
    const int warp_m = wid >> 2, warp_n = wid & 3;

    float acc[2][4][4];
    uint32_t hacc[2][4][2];
#pragma unroll
    for (int a = 0; a < 2; a++)
#pragma unroll
        for (int b = 0; b < 4; b++) {
#pragma unroll
            for (int c = 0; c < 4; c++) acc[a][b][c] = 0.f;
            hacc[a][b][0] = 0u; hacc[a][b][1] = 0u;
        }

    int rA[2], rW[2];
#pragma unroll
    for (int mt = 0; mt < 2; mt++) rA[mt] = warp_m * 32 + mt * 16 + (lane & 15);
#pragma unroll
    for (int nt2 = 0; nt2 < 2; nt2++) rW[nt2] = warp_n * 32 + nt2 * 16 + (lane & 15);
    const int khalf = lane >> 4;

    gstage(Ah, M, rowTile, Wh, Wl, colTile, 0, sbase, tid);
    cp_commit();

    for (int c = 0; c < 16; c++) {
        if (c + 1 < 16) {
            gstage(Ah, M, rowTile, Wh, Wl, colTile, (c + 1) * 64,
                   sbase + ((c + 1) & 1) * GT_BUF, tid);
            cp_commit();
            asm volatile("cp.async.wait_group 1;" ::: "memory");
        } else {
            asm volatile("cp.async.wait_group 0;" ::: "memory");
        }
        __syncthreads();

        const uint32_t bufb = sbase + (c & 1) * GT_BUF;
        const uint32_t sAh = bufb;
        const uint32_t sWh = bufb + GT_TILE, sWl = bufb + 2 * GT_TILE;

#pragma unroll
        for (int kq = 0; kq < 4; kq++) {
            const int kp = 2 * kq + khalf;
            uint32_t ah[2][4], wh[2][4], wl[2][4];
#pragma unroll
            for (int mt = 0; mt < 2; mt++) {
                const uint32_t off = (rA[mt] << 7) + ((kp ^ (rA[mt] & 7)) << 4);
                ldm4(ah[mt], sAh + off);
            }
#pragma unroll
            for (int nt2 = 0; nt2 < 2; nt2++) {
                const uint32_t off = (rW[nt2] << 7) + ((kp ^ (rW[nt2] & 7)) << 4);
                ldm4(wh[nt2], sWh + off);
                ldm4(wl[nt2], sWl + off);
            }
#pragma unroll
            for (int mt = 0; mt < 2; mt++) {
#pragma unroll
                for (int nt = 0; nt < 4; nt++) {
                    const uint32_t* whf = wh[nt >> 1];
                    mma16816(acc[mt][nt], ah[mt], whf[nt & 1], whf[(nt & 1) + 2]);
                }
            }
#pragma unroll
            for (int mt = 0; mt < 2; mt++) {
#pragma unroll
                for (int nt = 0; nt < 4; nt++) {
                    const uint32_t* wlf = wl[nt >> 1];
                    mma16816h(hacc[mt][nt], ah[mt], wlf[nt & 1], wlf[(nt & 1) + 2]);
                }
            }
        }
        __syncthreads();
    }

    const int g = lane >> 2, tg = lane & 3;
#pragma unroll
    for (int mt = 0; mt < 2; mt++) {
#pragma unroll
        for (int nt = 0; nt < 4; nt++) {
            const int n0 = colTile + warp_n * 32 + nt * 8 + tg * 2;
            const float2 bv = *(const float2*)(bias + n0);
            const __half2 hc0 = *(const __half2*)&hacc[mt][nt][0];
            const __half2 hc1 = *(const __half2*)&hacc[mt][nt][1];
#pragma unroll
            for (int hf = 0; hf < 2; hf++) {
                const int m = rowTile + warp_m * 32 + mt * 16 + g + hf * 8;
                if (m >= M) continue;
                const __half2 hc = hf ? hc1 : hc0;
                float v0 = acc[mt][nt][hf * 2 + 0] + __low2float(hc) + bv.x;
                float v1 = acc[mt][nt][hf * 2 + 1] + __high2float(hc) + bv.y;
                if (MODE == 0) {
                    float2 o; o.x = v0; o.y = v1;
                    *(float2*)(outf + (long long)m * 1024 + n0) = o;
                } else {
                    int b_, nn;
                    if (MODE == 1) { b_ = m >> 11; nn = m & 2047; }
                    else           { b_ = m >> 4;  nn = NVID + (m & 15); }
                    const int hh = n0 >> 6, d = n0 & 63;
                    if (MODE == 1 && rk && d < 60) {
                        const int seg = d / 20, jj = (d - seg * 20) >> 1;
                        const int pos = (seg == 0) ? (nn >> 8)
                                      : (seg == 1) ? ((nn >> 4) & 15) : (nn & 15);
                        const float omega = ex2f(-(float)jj * 1.3287712379549449f);
                        float sn, cs;
                        sincosf((float)pos * omega, &sn, &cs);
                        const float x1 = v0 * cs - v1 * sn;
                        const float x2 = v1 * cs + v0 * sn;
                        v0 = x1; v1 = x2;
                    }
                    if (rk == 1) { v0 *= QSC; v1 *= QSC; }
                    const long long idx = (((long long)(b_ * HEADS + hh)) * NTOT + nn) * HD + d;
                    *(ushort2*)(oh + idx) = make_ushort2(h16(v0), h16(v1));
                }
            }
        }
    }
}

// grid (8, 33, 3): z = {q,k,v}; by<32 video rows; by==32 action rows
__global__ __launch_bounds__(512, 1)
void gemm_qkv_mma(const float* bq, const float* bk, const float* bv,
                  const float* bqa, const float* bka, const float* bva)
{
    const int z = blockIdx.z;
    const bool act = (blockIdx.y == 32);
    const unsigned short* Ah = g_bh + (act ? OFF_ACTION : OFF_VIDEO);
    const int M = act ? (BSZ * NACT) : (BSZ * NVID);
    const int rowTile = act ? 0 : blockIdx.y * 128;
    const int colTile = blockIdx.x * 128;
    const int widx = z + (act ? 3 : 0);
    const unsigned short* Wh = g_bh + OFF_W + widx * WSZ;
    const unsigned short* Wl = g_bl + OFF_W + widx * WSZ;
    const float* bias = act ? (z == 0 ? bqa : (z == 1 ? bka : bva))
                            : (z == 0 ? bq : (z == 1 ? bk : bv));
    unsigned short* oh;
    int rk;
    if (z == 0)      { oh = g_qh; rk = 1; }
    else if (z == 1) { oh = g_kh; rk = 2; }
    else             { oh = g_vh; rk = 0; }
    if (act) gemm_body<2>(Ah, M, rowTile, Wh, Wl, colTile, bias, nullptr, oh, rk);
    else     gemm_body<1>(Ah, M, rowTile, Wh, Wl, colTile, bias, nullptr, oh, rk);
}

// grid (8, 17, 2): z = batch; by<16 video rows; by==16 action rows
__global__ __launch_bounds__(512, 1)
void gemm_out_mma(const float* bp, const float* bpa, float* __restrict__ dout)
{
    const int z = blockIdx.z;
    const bool act = (blockIdx.y == 16);
    const long long aoff = OFF_CTX + (long long)z * NTOT * HIDDEN +
                           (act ? (long long)NVID * HIDDEN : 0);
    const unsigned short* Ah = g_bh + aoff;
    const int M = act ? NACT : NVID;
    const int rowTile = act ? 0 : blockIdx.y * 128;
    const int colTile = blockIdx.x * 128;
    const int widx = act ? 7 : 6;
    const unsigned short* Wh = g_bh + OFF_W + widx * WSZ;
    const unsigned short* Wl = g_bl + OFF_W + widx * WSZ;
    const float* bias = act ? bpa : bp;
    float* C = act ? (dout + (long long)BSZ * NVID * HIDDEN + (long long)z * NACT * HIDDEN)
                   : (dout + (long long)z * NVID * HIDDEN);
    gemm_body<0>(Ah, M, rowTile, Wh, Wl, colTile, bias, C, nullptr, 0);
}

// ================= flash attention: 64 q-rows, 4 warps, 4 CTAs/SM =================
// single-fp16 K/V; smem: Q 8K + 4 rotating 8K buffers = 40 KB -> 4 CTAs/SM.
#define AT_QOFF 0
#define AT_BUF(i) (8192 + (i) * 8192)
#define AT_SMEM (8192 + 4 * 8192)     // 40960

__device__ __forceinline__ void stage_t64(const unsigned short* src0,
                                          long long base, int kt, uint32_t bufb, int tid) {
#pragma unroll
    for (int i = 0; i < 4; i++) {
        const int t = (i << 7) + tid;            // 0..511
        const int row = t >> 3, c = t & 7;
        const int key = kt * 64 + row;
        const uint32_t dst = bufb + (row << 7) + ((c ^ (row & 7)) << 4);
        const unsigned short* s = src0 + base +
            (long long)(key < NTOT ? key : 0) * HD + c * 8;
        cpa16z(dst, s, (key < NTOT) ? 16 : 0);
    }
}

__global__ __launch_bounds__(128, 4)
void attn_mma()
{
    extern __shared__ char dsm[];
    const uint32_t sb = smem_u32(dsm);
    const int tid = threadIdx.x, lane = tid & 31, w = tid >> 5;   // 4 warps
    const int qt = blockIdx.x, bh = blockIdx.y;
    const int b = bh >> 4, h = bh & 15;
    const long long base = (long long)bh * NTOT * HD;
    const int g = lane >> 2, tg = lane & 3;
    const int khalf = lane >> 4, l15 = lane & 15;

    // prologue: G0 = {Q, K0}, G1 = {V0}, G2 = {K1}
#pragma unroll
    for (int i = 0; i < 4; i++) {
        const int t = (i << 7) + tid;
        const int row = t >> 3, c = t & 7;
        const int n = qt * 64 + row;
        const uint32_t dst = sb + AT_QOFF + (row << 7) + ((c ^ (row & 7)) << 4);
        const unsigned short* src = g_qh + base + (long long)(n < NTOT ? n : 0) * HD + c * 8;
        cpa16z(dst, src, (n < NTOT) ? 16 : 0);
    }
    stage_t64(g_kh, base, 0, sb + AT_BUF(0), tid);
    cp_commit();
    stage_t64(g_vh, base, 0, sb + AT_BUF(1), tid);
    cp_commit();
    stage_t64(g_kh, base, 1, sb + AT_BUF(2), tid);
    cp_commit();

    float oacc[8][4];
#pragma unroll
    for (int i = 0; i < 8; i++)
#pragma unroll
        for (int j = 0; j < 4; j++) oacc[i][j] = 0.f;
    float m0 = -1e30f, m1 = -1e30f, l0 = 0.f, l1 = 0.f;
    uint32_t qfh[4][4];

    const int NKT = 33;   // 33 * 64 = 2112 >= 2064
    for (int kt = 0; kt < NKT; kt++) {
        // K(kt) ready (pending after: V(kt), K(kt+1))
        asm volatile("cp.async.wait_group 2;" ::: "memory");
        __syncthreads();

        if (kt == 0) {   // Q fragments (once)
            const int row = w * 16 + l15;
#pragma unroll
            for (int kq = 0; kq < 4; kq++) {
                const int kp = 2 * kq + khalf;
                const uint32_t off = (row << 7) + ((kp ^ (row & 7)) << 4);
                ldm4(qfh[kq], sb + AT_QOFF + off);
            }
        }

        // prefetch V(kt+1) into V(kt-1)'s slot
        if (kt + 1 < NKT)
            stage_t64(g_vh, base, kt + 1, sb + AT_BUF(((kt + 1) & 1) * 2 + 1), tid);
        cp_commit();

        const uint32_t sKh = sb + AT_BUF((kt & 1) * 2);

        float sacc[8][4];
#pragma unroll
        for (int i = 0; i < 8; i++)
#pragma unroll
            for (int j = 0; j < 4; j++) sacc[i][j] = 0.f;

        // S = Qh*Kh, 64 keys
#pragma unroll
        for (int kq = 0; kq < 4; kq++) {
            const int kp = 2 * kq + khalf;
#pragma unroll
            for (int ng = 0; ng < 4; ng++) {
                const int row = ng * 16 + l15;
                const uint32_t off = (row << 7) + ((kp ^ (row & 7)) << 4);
                uint32_t kh4[4];
                ldm4(kh4, sKh + off);
                mma16816(sacc[2 * ng + 0], qfh[kq], kh4[0], kh4[2]);
                mma16816(sacc[2 * ng + 1], qfh[kq], kh4[1], kh4[3]);
            }
        }

        // mask + online softmax (base-2)
        const int kvalid = NTOT - kt * 64;
        if (kvalid < 64) {
#pragma unroll
            for (int nt = 0; nt < 8; nt++) {
                const int c0 = nt * 8 + 2 * tg;
                if (c0 >= kvalid)     { sacc[nt][0] = -1e30f; sacc[nt][2] = -1e30f; }
                if (c0 + 1 >= kvalid) { sacc[nt][1] = -1e30f; sacc[nt][3] = -1e30f; }
            }
        }
        float mx0 = -1e30f, mx1 = -1e30f;
#pragma unroll
        for (int nt = 0; nt < 8; nt++) {
            mx0 = fmaxf(mx0, fmaxf(sacc[nt][0], sacc[nt][1]));
            mx1 = fmaxf(mx1, fmaxf(sacc[nt][2], sacc[nt][3]));
        }
        mx0 = fmaxf(mx0, __shfl_xor_sync(0xffffffffu, mx0, 1));
        mx0 = fmaxf(mx0, __shfl_xor_sync(0xffffffffu, mx0, 2));
        mx1 = fmaxf(mx1, __shfl_xor_sync(0xffffffffu, mx1, 1));
        mx1 = fmaxf(mx1, __shfl_xor_sync(0xffffffffu, mx1, 2));
        const float mn0 = fmaxf(m0, mx0), mn1 = fmaxf(m1, mx1);
        const float cr0 = ex2f(m0 - mn0), cr1 = ex2f(m1 - mn1);
        m0 = mn0; m1 = mn1;
        float s0 = 0.f, s1 = 0.f;
#pragma unroll
        for (int nt = 0; nt < 8; nt++) {
            sacc[nt][0] = ex2f(sacc[nt][0] - mn0);
            sacc[nt][1] = ex2f(sacc[nt][1] - mn0);
            sacc[nt][2] = ex2f(sacc[nt][2] - mn1);
            sacc[nt][3] = ex2f(sacc[nt][3] - mn1);
            s0 += sacc[nt][0] + sacc[nt][1];
            s1 += sacc[nt][2] + sacc[nt][3];
        }
        s0 += __shfl_xor_sync(0xffffffffu, s0, 1);
        s0 += __shfl_xor_sync(0xffffffffu, s0, 2);
        s1 += __shfl_xor_sync(0xffffffffu, s1, 1);
        s1 += __shfl_xor_sync(0xffffffffu, s1, 2);
        l0 = l0 * cr0 + s0; l1 = l1 * cr1 + s1;
#pragma unroll
        for (int nt = 0; nt < 8; nt++) {
            oacc[nt][0] *= cr0; oacc[nt][1] *= cr0;
            oacc[nt][2] *= cr1; oacc[nt][3] *= cr1;
        }

        // V(kt) ready (pending after: K(kt+1), V(kt+1))
        asm volatile("cp.async.wait_group 2;" ::: "memory");
        __syncthreads();

        // prefetch K(kt+2) into K(kt)'s slot
        if (kt + 2 < NKT)
            stage_t64(g_kh, base, kt + 2, sb + AT_BUF((kt & 1) * 2), tid);
        cp_commit();

        const uint32_t sVh = sb + AT_BUF((kt & 1) * 2 + 1);

        // O += Ph*Vh
#pragma unroll
        for (int kc = 0; kc < 4; kc++) {
            uint32_t pah[4];
            const float* t0 = sacc[2 * kc];
            const float* t1 = sacc[2 * kc + 1];
            pah[0] = pkh(t0[0], t0[1]);
            pah[1] = pkh(t0[2], t0[3]);
            pah[2] = pkh(t1[0], t1[1]);
            pah[3] = pkh(t1[2], t1[3]);
            const int row = kc * 16 + l15;
#pragma unroll
            for (int ng = 0; ng < 4; ng++) {
                const int cc = 2 * ng + khalf;
                const uint32_t off = (row << 7) + ((cc ^ (row & 7)) << 4);
                uint32_t vh4[4];
                ldm4t(vh4, sVh + off);
                mma16816(oacc[2 * ng + 0], pah, vh4[0], vh4[1]);
                mma16816(oacc[2 * ng + 1], pah, vh4[2], vh4[3]);
            }
        }
    }

    // normalize + write ctx as fp16 (out-proj A side)
    const float iv0 = 1.f / l0, iv1 = 1.f / l1;
    const int n0 = qt * 64 + w * 16 + g;
    const int n1 = n0 + 8;
#pragma unroll
    for (int nt = 0; nt < 8; nt++) {
        const int d = nt * 8 + 2 * tg;
        if (n0 < NTOT) {
            const long long idx = OFF_CTX + ((long long)(b * NTOT + n0)) * HIDDEN + h * HD + d;
            *(ushort2*)(g_bh + idx) = make_ushort2(h16(oacc[nt][0] * iv0),
                                                   h16(oacc[nt][1] * iv0));
        }
        if (n1 < NTOT) {
            const long long idx = OFF_CTX + ((long long)(b * NTOT + n1)) * HIDDEN + h * HD + d;
            *(ushort2*)(g_bh + idx) = make_ushort2(h16(oacc[nt][2] * iv1),
                                                   h16(oacc[nt][3] * iv1));
        }
    }
}

// ---------------- host launcher ----------------
extern "C" void kernel_launch(void* const* d_in, const int* in_sizes, int n_in,
                              void* d_out, int out_size)
{
    (void)out_size;
    const float* video = nullptr;
    const float* action = nullptr;
    const float* wb[16];
    int wi = 0;
    for (int i = 0; i < n_in; i++) {
        const int sz = in_sizes[i];
        if (sz == BSZ * NVID * HIDDEN)       video  = (const float*)d_in[i];
        else if (sz == BSZ * NACT * HIDDEN)  action = (const float*)d_in[i];
        else if (wi < 16)                    wb[wi++] = (const float*)d_in[i];
    }
    float* out = (float*)d_out;

    cudaFuncSetAttribute(gemm_qkv_mma, cudaFuncAttributeMaxDynamicSharedMemorySize, GT_SMEM);
    cudaFuncSetAttribute(gemm_out_mma, cudaFuncAttributeMaxDynamicSharedMemorySize, GT_SMEM);
    cudaFuncSetAttribute(attn_mma, cudaFuncAttributeMaxDynamicSharedMemorySize, AT_SMEM);

    // split inputs + weights into fp16 hi/lo
    cvt_all<<<dim3(1024, 10), 256>>>(video, action, wb[0], wb[2], wb[4], wb[6],
                                     wb[8], wb[10], wb[12], wb[14]);

    // QKV projections (rope + scale fused in epilogue)
    gemm_qkv_mma<<<dim3(8, 33, 3), 512, GT_SMEM>>>(wb[1], wb[3], wb[5],
                                                   wb[7], wb[9], wb[11]);

    // attention: 64-q-row CTAs, 4 CTAs/SM, single-fp16 K/V
    attn_mma<<<dim3(33, 32), 128, AT_SMEM>>>();

    // output projection
    gemm_out_mma<<<dim3(8, 17, 2), 512, GT_SMEM>>>(wb[13], wb[15], out);
}

// round 12
// speedup vs baseline: 2.2764x; 1.2830x over previous
#include <cuda_runtime.h>
#include <cuda_fp16.h>
#include <cstdint>

#define HIDDEN 1024
#define HEADS 16
#define HD 64
#define NVID 2048
#define NACT 16
#define NTOT 2064
#define BSZ 2
#define BH (BSZ*HEADS)
// q pre-scale: ATT_SCALE * log2(e), so softmax uses exp2
#define QSC 0.18033688011112042f

#define WSZ 1048576LL
#define OFF_VIDEO 0LL
#define OFF_ACTION 4194304LL
#define OFF_W 4227072LL
#define OFF_CTX (OFF_W + 8LL * WSZ)
#define BF_TOTAL (OFF_CTX + 4227072LL)

// ---------------- scratch (device globals; no allocation allowed) ----------------
__device__ unsigned short g_bh[BF_TOTAL];    // fp16: inputs, weights, ctx
__device__ unsigned short g_qh[BH * NTOT * HD];
__device__ unsigned short g_kh[BH * NTOT * HD];
__device__ unsigned short g_vh[BH * NTOT * HD];

// ---------------- helpers ----------------
__device__ __forceinline__ void cpa16z(uint32_t dst, const void* src, int bytes) {
    asm volatile("cp.async.cg.shared.global [%0], [%1], 16, %2;"
                 :: "r"(dst), "l"(src), "r"(bytes) : "memory");
}
__device__ __forceinline__ void cp_commit() {
    asm volatile("cp.async.commit_group;" ::: "memory");
}
__device__ __forceinline__ uint32_t smem_u32(const void* p) {
    return (uint32_t)__cvta_generic_to_shared(p);
}
__device__ __forceinline__ void ldm4(uint32_t* r, uint32_t addr) {
    asm volatile("ldmatrix.sync.aligned.m8n8.x4.shared.b16 {%0,%1,%2,%3}, [%4];"
                 : "=r"(r[0]), "=r"(r[1]), "=r"(r[2]), "=r"(r[3]) : "r"(addr));
}
__device__ __forceinline__ void ldm4t(uint32_t* r, uint32_t addr) {
    asm volatile("ldmatrix.sync.aligned.m8n8.x4.trans.shared.b16 {%0,%1,%2,%3}, [%4];"
                 : "=r"(r[0]), "=r"(r[1]), "=r"(r[2]), "=r"(r[3]) : "r"(addr));
}
__device__ __forceinline__ void mma16816(float* c, const uint32_t* a,
                                         uint32_t b0, uint32_t b1) {
    asm volatile("mma.sync.aligned.m16n8k16.row.col.f32.f16.f16.f32 "
                 "{%0,%1,%2,%3}, {%4,%5,%6,%7}, {%8,%9}, {%0,%1,%2,%3};"
                 : "+f"(c[0]), "+f"(c[1]), "+f"(c[2]), "+f"(c[3])
                 : "r"(a[0]), "r"(a[1]), "r"(a[2]), "r"(a[3]), "r"(b0), "r"(b1));
}
__device__ __forceinline__ unsigned short h16(float x) {
    return __half_as_ushort(__float2half_rn(x));
}
__device__ __forceinline__ uint32_t pkh(float lo, float hi) {
    uint32_t r;
    asm("cvt.rn.f16x2.f32 %0, %1, %2;" : "=r"(r) : "f"(hi), "f"(lo));
    return r;
}
__device__ __forceinline__ float ex2f(float x) {
    float y; asm("ex2.approx.ftz.f32 %0, %1;" : "=f"(y) : "f"(x)); return y;
}

// ---------------- fp32 -> fp16 convert (inputs + weights) ----------------
__global__ void cvt_all(const float* v, const float* a,
                        const float* w0, const float* w1, const float* w2,
                        const float* w3, const float* w4, const float* w5,
                        const float* w6, const float* w7)
{
    const float* srcs[10] = { v, a, w0, w1, w2, w3, w4, w5, w6, w7 };
    const long long offs[10] = { OFF_VIDEO, OFF_ACTION,
        OFF_W + 0 * WSZ, OFF_W + 1 * WSZ, OFF_W + 2 * WSZ, OFF_W + 3 * WSZ,
        OFF_W + 4 * WSZ, OFF_W + 5 * WSZ, OFF_W + 6 * WSZ, OFF_W + 7 * WSZ };
    const int cnts[10] = { 4194304, 32768, 1048576, 1048576, 1048576, 1048576,
                           1048576, 1048576, 1048576, 1048576 };
    const int z = blockIdx.y;
    const float4* src = (const float4*)srcs[z];
    ushort4* hi = (ushort4*)(g_bh + offs[z]);
    const int n4 = cnts[z] >> 2;
    for (int i = blockIdx.x * blockDim.x + threadIdx.x; i < n4;
         i += gridDim.x * blockDim.x) {
        const float4 x = src[i];
        ushort4 h;
        h.x = h16(x.x); h.y = h16(x.y); h.z = h16(x.z); h.w = h16(x.w);
        hi[i] = h;
    }
}

// ================= mma.sync fp16 GEMM (projections), 512 threads =================
// C = A * W, single fp16 operands, fp32 accum.
#define GT_TILE 16384
#define GT_BUF  (2 * GT_TILE)
#define GT_SMEM (2 * GT_BUF)          // 64 KB

__device__ __forceinline__ void gstage(const unsigned short* Ah,
                                       int M, int rowTile,
                                       const unsigned short* Wh,
                                       int colTile, int k0, uint32_t bufb, int tid)
{
#pragma unroll
    for (int i = 0; i < 4; i++) {
        const int tile = i >> 1;
        const int t = ((i & 1) << 9) + tid;
        const int row = t >> 3, c = t & 7;
        const uint32_t dst = bufb + tile * GT_TILE + (row << 7) + ((c ^ (row & 7)) << 4);
        if (tile == 0) {
            const int m = rowTile + row;
            const int mm = (m < M) ? m : 0;
            cpa16z(dst, Ah + (long long)mm * 1024 + k0 + c * 8, (m < M) ? 16 : 0);
        } else {
            cpa16z(dst, Wh + (long long)(colTile + row) * 1024 + k0 + c * 8, 16);
        }
    }
}

// MODE 0: fp32 out[m*1024+n];  MODE 1: video qkv + rope;  MODE 2: action qkv
template <int MODE>
__device__ __forceinline__ void gemm_body(const unsigned short* Ah,
                                          int M, int rowTile,
                                          const unsigned short* Wh,
                                          int colTile, const float* bias,
                                          float* __restrict__ outf,
                                          unsigned short* __restrict__ oh, int rk)
{
    extern __shared__ char dsmem[];
    const uint32_t sbase = smem_u32(dsmem);
    const int tid = threadIdx.x;
    const int lane = tid & 31, wid = tid >> 5;
    const int warp_m = wid >> 2, warp_n = wid & 3;

    float acc[2][4][4];
#pragma unroll
    for (int a = 0; a < 2; a++)
#pragma unroll
        for (int b = 0; b < 4; b++)
#pragma unroll
            for (int c = 0; c < 4; c++) acc[a][b][c] = 0.f;

    int rA[2], rW[2];
#pragma unroll
    for (int mt = 0; mt < 2; mt++) rA[mt] = warp_m * 32 + mt * 16 + (lane & 15);
#pragma unroll
    for (int nt2 = 0; nt2 < 2; nt2++) rW[nt2] = warp_n * 32 + nt2 * 16 + (lane & 15);
    const int khalf = lane >> 4;

    gstage(Ah, M, rowTile, Wh, colTile, 0, sbase, tid);
    cp_commit();

    for (int c = 0; c < 16; c++) {
        if (c + 1 < 16) {
            gstage(Ah, M, rowTile, Wh, colTile, (c + 1) * 64,
                   sbase + ((c + 1) & 1) * GT_BUF, tid);
            cp_commit();
            asm volatile("cp.async.wait_group 1;" ::: "memory");
        } else {
            asm volatile("cp.async.wait_group 0;" ::: "memory");
        }
        __syncthreads();

        const uint32_t bufb = sbase + (c & 1) * GT_BUF;
        const uint32_t sAh = bufb;
        const uint32_t sWh = bufb + GT_TILE;

#pragma unroll
        for (int kq = 0; kq < 4; kq++) {
            const int kp = 2 * kq + khalf;
            uint32_t ah[2][4], wh[2][4];
#pragma unroll
            for (int mt = 0; mt < 2; mt++) {
                const uint32_t off = (rA[mt] << 7) + ((kp ^ (rA[mt] & 7)) << 4);
                ldm4(ah[mt], sAh + off);
            }
#pragma unroll
            for (int nt2 = 0; nt2 < 2; nt2++) {
                const uint32_t off = (rW[nt2] << 7) + ((kp ^ (rW[nt2] & 7)) << 4);
                ldm4(wh[nt2], sWh + off);
            }
#pragma unroll
            for (int mt = 0; mt < 2; mt++) {
#pragma unroll
                for (int nt = 0; nt < 4; nt++) {
                    const uint32_t* whf = wh[nt >> 1];
                    mma16816(acc[mt][nt], ah[mt], whf[nt & 1], whf[(nt & 1) + 2]);
                }
            }
        }
        __syncthreads();
    }

    const int g = lane >> 2, tg = lane & 3;
#pragma unroll
    for (int mt = 0; mt < 2; mt++) {
#pragma unroll
        for (int nt = 0; nt < 4; nt++) {
            const int n0 = colTile + warp_n * 32 + nt * 8 + tg * 2;
            const float2 bv = *(const float2*)(bias + n0);
#pragma unroll
            for (int hf = 0; hf < 2; hf++) {
                const int m = rowTile + warp_m * 32 + mt * 16 + g + hf * 8;
                if (m >= M) continue;
                float v0 = acc[mt][nt][hf * 2 + 0] + bv.x;
                float v1 = acc[mt][nt][hf * 2 + 1] + bv.y;
                if (MODE == 0) {
                    float2 o; o.x = v0; o.y = v1;
                    *(float2*)(outf + (long long)m * 1024 + n0) = o;
                } else {
                    int b_, nn;
                    if (MODE == 1) { b_ = m >> 11; nn = m & 2047; }
                    else           { b_ = m >> 4;  nn = NVID + (m & 15); }
                    const int hh = n0 >> 6, d = n0 & 63;
                    if (MODE == 1 && rk && d < 60) {
                        const int seg = d / 20, jj = (d - seg * 20) >> 1;
                        const int pos = (seg == 0) ? (nn >> 8)
                                      : (seg == 1) ? ((nn >> 4) & 15) : (nn & 15);
                        const float omega = ex2f(-(float)jj * 1.3287712379549449f);
                        float sn, cs;
                        sincosf((float)pos * omega, &sn, &cs);
                        const float x1 = v0 * cs - v1 * sn;
                        const float x2 = v1 * cs + v0 * sn;
                        v0 = x1; v1 = x2;
                    }
                    if (rk == 1) { v0 *= QSC; v1 *= QSC; }
                    const long long idx = (((long long)(b_ * HEADS + hh)) * NTOT + nn) * HD + d;
                    *(ushort2*)(oh + idx) = make_ushort2(h16(v0), h16(v1));
                }
            }
        }
    }
}

// grid (8, 33, 3): z = {q,k,v}; by<32 video rows; by==32 action rows
__global__ __launch_bounds__(512, 1)
void gemm_qkv_mma(const float* bq, const float* bk, const float* bv,
                  const float* bqa, const float* bka, const float* bva)
{
    const int z = blockIdx.z;
    const bool act = (blockIdx.y == 32);
    const unsigned short* Ah = g_bh + (act ? OFF_ACTION : OFF_VIDEO);
    const int M = act ? (BSZ * NACT) : (BSZ * NVID);
    const int rowTile = act ? 0 : blockIdx.y * 128;
    const int colTile = blockIdx.x * 128;
    const int widx = z + (act ? 3 : 0);
    const unsigned short* Wh = g_bh + OFF_W + widx * WSZ;
    const float* bias = act ? (z == 0 ? bqa : (z == 1 ? bka : bva))
                            : (z == 0 ? bq : (z == 1 ? bk : bv));
    unsigned short* oh;
    int rk;
    if (z == 0)      { oh = g_qh; rk = 1; }
    else if (z == 1) { oh = g_kh; rk = 2; }
    else             { oh = g_vh; rk = 0; }
    if (act) gemm_body<2>(Ah, M, rowTile, Wh, colTile, bias, nullptr, oh, rk);
    else     gemm_body<1>(Ah, M, rowTile, Wh, colTile, bias, nullptr, oh, rk);
}

// grid (8, 17, 2): z = batch; by<16 video rows; by==16 action rows
__global__ __launch_bounds__(512, 1)
void gemm_out_mma(const float* bp, const float* bpa, float* __restrict__ dout)
{
    const int z = blockIdx.z;
    const bool act = (blockIdx.y == 16);
    const long long aoff = OFF_CTX + (long long)z * NTOT * HIDDEN +
                           (act ? (long long)NVID * HIDDEN : 0);
    const unsigned short* Ah = g_bh + aoff;
    const int M = act ? NACT : NVID;
    const int rowTile = act ? 0 : blockIdx.y * 128;
    const int colTile = blockIdx.x * 128;
    const int widx = act ? 7 : 6;
    const unsigned short* Wh = g_bh + OFF_W + widx * WSZ;
    const float* bias = act ? bpa : bp;
    float* C = act ? (dout + (long long)BSZ * NVID * HIDDEN + (long long)z * NACT * HIDDEN)
                   : (dout + (long long)z * NVID * HIDDEN);
    gemm_body<0>(Ah, M, rowTile, Wh, colTile, bias, C, nullptr, 0);
}

// ================= flash attention: 64 q-rows, 4 warps, 4 CTAs/SM =================
#define AT_QOFF 0
#define AT_BUF(i) (8192 + (i) * 8192)
#define AT_SMEM (8192 + 4 * 8192)     // 40960

__device__ __forceinline__ void stage_t64(const unsigned short* src0,
                                          long long base, int kt, uint32_t bufb, int tid) {
#pragma unroll
    for (int i = 0; i < 4; i++) {
        const int t = (i << 7) + tid;
        const int row = t >> 3, c = t & 7;
        const int key = kt * 64 + row;
        const uint32_t dst = bufb + (row << 7) + ((c ^ (row & 7)) << 4);
        const unsigned short* s = src0 + base +
            (long long)(key < NTOT ? key : 0) * HD + c * 8;
        cpa16z(dst, s, (key < NTOT) ? 16 : 0);
    }
}

__global__ __launch_bounds__(128, 4)
void attn_mma()
{
    extern __shared__ char dsm[];
    const uint32_t sb = smem_u32(dsm);
    const int tid = threadIdx.x, lane = tid & 31, w = tid >> 5;
    const int qt = blockIdx.x, bh = blockIdx.y;
    const int b = bh >> 4, h = bh & 15;
    const long long base = (long long)bh * NTOT * HD;
    const int g = lane >> 2, tg = lane & 3;
    const int khalf = lane >> 4, l15 = lane & 15;

#pragma unroll
    for (int i = 0; i < 4; i++) {
        const int t = (i << 7) + tid;
        const int row = t >> 3, c = t & 7;
        const int n = qt * 64 + row;
        const uint32_t dst = sb + AT_QOFF + (row << 7) + ((c ^ (row & 7)) << 4);
        const unsigned short* src = g_qh + base + (long long)(n < NTOT ? n : 0) * HD + c * 8;
        cpa16z(dst, src, (n < NTOT) ? 16 : 0);
    }
    stage_t64(g_kh, base, 0, sb + AT_BUF(0), tid);
    cp_commit();
    stage_t64(g_vh, base, 0, sb + AT_BUF(1), tid);
    cp_commit();
    stage_t64(g_kh, base, 1, sb + AT_BUF(2), tid);
    cp_commit();

    float oacc[8][4];
#pragma unroll
    for (int i = 0; i < 8; i++)
#pragma unroll
        for (int j = 0; j < 4; j++) oacc[i][j] = 0.f;
    float m0 = -1e30f, m1 = -1e30f, l0 = 0.f, l1 = 0.f;
    uint32_t qfh[4][4];

    const int NKT = 33;
    for (int kt = 0; kt < NKT; kt++) {
        asm volatile("cp.async.wait_group 2;" ::: "memory");
        __syncthreads();

        if (kt == 0) {
            const int row = w * 16 + l15;
#pragma unroll
            for (int kq = 0; kq < 4; kq++) {
                const int kp = 2 * kq + khalf;
                const uint32_t off = (row << 7) + ((kp ^ (row & 7)) << 4);
                ldm4(qfh[kq], sb + AT_QOFF + off);
            }
        }

        if (kt + 1 < NKT)
            stage_t64(g_vh, base, kt + 1, sb + AT_BUF(((kt + 1) & 1) * 2 + 1), tid);
        cp_commit();

        const uint32_t sKh = sb + AT_BUF((kt & 1) * 2);

        float sacc[8][4];
#pragma unroll
        for (int i = 0; i < 8; i++)
#pragma unroll
            for (int j = 0; j < 4; j++) sacc[i][j] = 0.f;

#pragma unroll
        for (int kq = 0; kq < 4; kq++) {
            const int kp = 2 * kq + khalf;
#pragma unroll
            for (int ng = 0; ng < 4; ng++) {
                const int row = ng * 16 + l15;
                const uint32_t off = (row << 7) + ((kp ^ (row & 7)) << 4);
                uint32_t kh4[4];
                ldm4(kh4, sKh + off);
                mma16816(sacc[2 * ng + 0], qfh[kq], kh4[0], kh4[2]);
                mma16816(sacc[2 * ng + 1], qfh[kq], kh4[1], kh4[3]);
            }
        }

        const int kvalid = NTOT - kt * 64;
        if (kvalid < 64) {
#pragma unroll
            for (int nt = 0; nt < 8; nt++) {
                const int c0 = nt * 8 + 2 * tg;
                if (c0 >= kvalid)     { sacc[nt][0] = -1e30f; sacc[nt][2] = -1e30f; }
                if (c0 + 1 >= kvalid) { sacc[nt][1] = -1e30f; sacc[nt][3] = -1e30f; }
            }
        }
        float mx0 = -1e30f, mx1 = -1e30f;
#pragma unroll
        for (int nt = 0; nt < 8; nt++) {
            mx0 = fmaxf(mx0, fmaxf(sacc[nt][0], sacc[nt][1]));
            mx1 = fmaxf(mx1, fmaxf(sacc[nt][2], sacc[nt][3]));
        }
        mx0 = fmaxf(mx0, __shfl_xor_sync(0xffffffffu, mx0, 1));
        mx0 = fmaxf(mx0, __shfl_xor_sync(0xffffffffu, mx0, 2));
        mx1 = fmaxf(mx1, __shfl_xor_sync(0xffffffffu, mx1, 1));
        mx1 = fmaxf(mx1, __shfl_xor_sync(0xffffffffu, mx1, 2));
        const float mn0 = fmaxf(m0, mx0), mn1 = fmaxf(m1, mx1);
        const float cr0 = ex2f(m0 - mn0), cr1 = ex2f(m1 - mn1);
        m0 = mn0; m1 = mn1;
        float s0 = 0.f, s1 = 0.f;
#pragma unroll
        for (int nt = 0; nt < 8; nt++) {
            sacc[nt][0] = ex2f(sacc[nt][0] - mn0);
            sacc[nt][1] = ex2f(sacc[nt][1] - mn0);
            sacc[nt][2] = ex2f(sacc[nt][2] - mn1);
            sacc[nt][3] = ex2f(sacc[nt][3] - mn1);
            s0 += sacc[nt][0] + sacc[nt][1];
            s1 += sacc[nt][2] + sacc[nt][3];
        }
        s0 += __shfl_xor_sync(0xffffffffu, s0, 1);
        s0 += __shfl_xor_sync(0xffffffffu, s0, 2);
        s1 += __shfl_xor_sync(0xffffffffu, s1, 1);
        s1 += __shfl_xor_sync(0xffffffffu, s1, 2);
        l0 = l0 * cr0 + s0; l1 = l1 * cr1 + s1;
#pragma unroll
        for (int nt = 0; nt < 8; nt++) {
            oacc[nt][0] *= cr0; oacc[nt][1] *= cr0;
            oacc[nt][2] *= cr1; oacc[nt][3] *= cr1;
        }

        asm volatile("cp.async.wait_group 2;" ::: "memory");
        __syncthreads();

        if (kt + 2 < NKT)
            stage_t64(g_kh, base, kt + 2, sb + AT_BUF((kt & 1) * 2), tid);
        cp_commit();

        const uint32_t sVh = sb + AT_BUF((kt & 1) * 2 + 1);

#pragma unroll
        for (int kc = 0; kc < 4; kc++) {
            uint32_t pah[4];
            const float* t0 = sacc[2 * kc];
            const float* t1 = sacc[2 * kc + 1];
            pah[0] = pkh(t0[0], t0[1]);
            pah[1] = pkh(t0[2], t0[3]);
            pah[2] = pkh(t1[0], t1[1]);
            pah[3] = pkh(t1[2], t1[3]);
            const int row = kc * 16 + l15;
#pragma unroll
            for (int ng = 0; ng < 4; ng++) {
                const int cc = 2 * ng + khalf;
                const uint32_t off = (row << 7) + ((cc ^ (row & 7)) << 4);
                uint32_t vh4[4];
                ldm4t(vh4, sVh + off);
                mma16816(oacc[2 * ng + 0], pah, vh4[0], vh4[1]);
                mma16816(oacc[2 * ng + 1], pah, vh4[2], vh4[3]);
            }
        }
    }

    // normalize + write ctx as fp16 (out-proj A side)
    const float iv0 = 1.f / l0, iv1 = 1.f / l1;
    const int n0 = qt * 64 + w * 16 + g;
    const int n1 = n0 + 8;
#pragma unroll
    for (int nt = 0; nt < 8; nt++) {
        const int d = nt * 8 + 2 * tg;
        if (n0 < NTOT) {
            const long long idx = OFF_CTX + ((long long)(b * NTOT + n0)) * HIDDEN + h * HD + d;
            *(ushort2*)(g_bh + idx) = make_ushort2(h16(oacc[nt][0] * iv0),
                                                   h16(oacc[nt][1] * iv0));
        }
        if (n1 < NTOT) {
            const long long idx = OFF_CTX + ((long long)(b * NTOT + n1)) * HIDDEN + h * HD + d;
            *(ushort2*)(g_bh + idx) = make_ushort2(h16(oacc[nt][2] * iv1),
                                                   h16(oacc[nt][3] * iv1));
        }
    }
}

// ---------------- host launcher ----------------
extern "C" void kernel_launch(void* const* d_in, const int* in_sizes, int n_in,
                              void* d_out, int out_size)
{
    (void)out_size;
    const float* video = nullptr;
    const float* action = nullptr;
    const float* wb[16];
    int wi = 0;
    for (int i = 0; i < n_in; i++) {
        const int sz = in_sizes[i];
        if (sz == BSZ * NVID * HIDDEN)       video  = (const float*)d_in[i];
        else if (sz == BSZ * NACT * HIDDEN)  action = (const float*)d_in[i];
        else if (wi < 16)                    wb[wi++] = (const float*)d_in[i];
    }
    float* out = (float*)d_out;

    cudaFuncSetAttribute(gemm_qkv_mma, cudaFuncAttributeMaxDynamicSharedMemorySize, GT_SMEM);
    cudaFuncSetAttribute(gemm_out_mma, cudaFuncAttributeMaxDynamicSharedMemorySize, GT_SMEM);
    cudaFuncSetAttribute(attn_mma, cudaFuncAttributeMaxDynamicSharedMemorySize, AT_SMEM);

    // convert inputs + weights to fp16
    cvt_all<<<dim3(1024, 10), 256>>>(video, action, wb[0], wb[2], wb[4], wb[6],
                                     wb[8], wb[10], wb[12], wb[14]);

    // QKV projections (rope + scale fused in epilogue)
    gemm_qkv_mma<<<dim3(8, 33, 3), 512, GT_SMEM>>>(wb[1], wb[3], wb[5],
                                                   wb[7], wb[9], wb[11]);

    // attention: 64-q-row CTAs, 4 CTAs/SM
    attn_mma<<<dim3(33, 32), 128, AT_SMEM>>>();

    // output projection
    gemm_out_mma<<<dim3(8, 17, 2), 512, GT_SMEM>>>(wb[13], wb[15], out);
}

// round 13
// speedup vs baseline: 2.5007x; 1.0985x over previous
#include <cuda_runtime.h>
#include <cuda_fp16.h>
#include <cstdint>

#define HIDDEN 1024
#define HEADS 16
#define HD 64
#define NVID 2048
#define NACT 16
#define NTOT 2064
#define BSZ 2
#define BH (BSZ*HEADS)
// q pre-scale: ATT_SCALE * log2(e), so softmax uses exp2
#define QSC 0.18033688011112042f

#define WSZ 1048576LL
#define OFF_VIDEO 0LL
#define OFF_ACTION 4194304LL
#define OFF_W 4227072LL
#define OFF_CTX (OFF_W + 8LL * WSZ)
#define BF_TOTAL (OFF_CTX + 4227072LL)

// ---------------- scratch (device globals; no allocation allowed) ----------------
__device__ unsigned short g_bh[BF_TOTAL];    // fp16: inputs, weights, ctx
__device__ unsigned short g_qh[BH * NTOT * HD];
__device__ unsigned short g_kh[BH * NTOT * HD];
__device__ unsigned short g_vh[BH * NTOT * HD];

// ---------------- helpers ----------------
__device__ __forceinline__ void cpa16z(uint32_t dst, const void* src, int bytes) {
    asm volatile("cp.async.cg.shared.global [%0], [%1], 16, %2;"
                 :: "r"(dst), "l"(src), "r"(bytes) : "memory");
}
__device__ __forceinline__ void cp_commit() {
    asm volatile("cp.async.commit_group;" ::: "memory");
}
__device__ __forceinline__ uint32_t smem_u32(const void* p) {
    return (uint32_t)__cvta_generic_to_shared(p);
}
__device__ __forceinline__ void ldm4(uint32_t* r, uint32_t addr) {
    asm volatile("ldmatrix.sync.aligned.m8n8.x4.shared.b16 {%0,%1,%2,%3}, [%4];"
                 : "=r"(r[0]), "=r"(r[1]), "=r"(r[2]), "=r"(r[3]) : "r"(addr));
}
__device__ __forceinline__ void ldm4t(uint32_t* r, uint32_t addr) {
    asm volatile("ldmatrix.sync.aligned.m8n8.x4.trans.shared.b16 {%0,%1,%2,%3}, [%4];"
                 : "=r"(r[0]), "=r"(r[1]), "=r"(r[2]), "=r"(r[3]) : "r"(addr));
}
__device__ __forceinline__ void mma16816(float* c, const uint32_t* a,
                                         uint32_t b0, uint32_t b1) {
    asm volatile("mma.sync.aligned.m16n8k16.row.col.f32.f16.f16.f32 "
                 "{%0,%1,%2,%3}, {%4,%5,%6,%7}, {%8,%9}, {%0,%1,%2,%3};"
                 : "+f"(c[0]), "+f"(c[1]), "+f"(c[2]), "+f"(c[3])
                 : "r"(a[0]), "r"(a[1]), "r"(a[2]), "r"(a[3]), "r"(b0), "r"(b1));
}
__device__ __forceinline__ unsigned short h16(float x) {
    return __half_as_ushort(__float2half_rn(x));
}
__device__ __forceinline__ uint32_t pkh(float lo, float hi) {
    uint32_t r;
    asm("cvt.rn.f16x2.f32 %0, %1, %2;" : "=r"(r) : "f"(hi), "f"(lo));
    return r;
}
__device__ __forceinline__ float ex2f(float x) {
    float y; asm("ex2.approx.ftz.f32 %0, %1;" : "=f"(y) : "f"(x)); return y;
}

// ---------------- fp32 -> fp16 convert (inputs + weights), 16B stores ----------------
__global__ void cvt_all(const float* v, const float* a,
                        const float* w0, const float* w1, const float* w2,
                        const float* w3, const float* w4, const float* w5,
                        const float* w6, const float* w7)
{
    const float* srcs[10] = { v, a, w0, w1, w2, w3, w4, w5, w6, w7 };
    const long long offs[10] = { OFF_VIDEO, OFF_ACTION,
        OFF_W + 0 * WSZ, OFF_W + 1 * WSZ, OFF_W + 2 * WSZ, OFF_W + 3 * WSZ,
        OFF_W + 4 * WSZ, OFF_W + 5 * WSZ, OFF_W + 6 * WSZ, OFF_W + 7 * WSZ };
    const int cnts[10] = { 4194304, 32768, 1048576, 1048576, 1048576, 1048576,
                           1048576, 1048576, 1048576, 1048576 };
    const int z = blockIdx.y;
    const float4* src = (const float4*)srcs[z];
    uint4* dst = (uint4*)(g_bh + offs[z]);
    const int n8 = cnts[z] >> 3;     // 8 fp16 = one uint4 store
    for (int i = blockIdx.x * blockDim.x + threadIdx.x; i < n8;
         i += gridDim.x * blockDim.x) {
        const float4 x = src[2 * i];
        const float4 y = src[2 * i + 1];
        uint4 o;
        o.x = pkh(x.x, x.y);
        o.y = pkh(x.z, x.w);
        o.z = pkh(y.x, y.y);
        o.w = pkh(y.z, y.w);
        dst[i] = o;
    }
}

// ================= mma.sync fp16 GEMM (projections), 512 threads =================
#define GT_TILE 16384
#define GT_BUF  (2 * GT_TILE)
#define GT_SMEM (2 * GT_BUF)          // 64 KB

__device__ __forceinline__ void gstage(const unsigned short* Ah,
                                       int M, int rowTile,
                                       const unsigned short* Wh,
                                       int colTile, int k0, uint32_t bufb, int tid)
{
#pragma unroll
    for (int i = 0; i < 4; i++) {
        const int tile = i >> 1;
        const int t = ((i & 1) << 9) + tid;
        const int row = t >> 3, c = t & 7;
        const uint32_t dst = bufb + tile * GT_TILE + (row << 7) + ((c ^ (row & 7)) << 4);
        if (tile == 0) {
            const int m = rowTile + row;
            const int mm = (m < M) ? m : 0;
            cpa16z(dst, Ah + (long long)mm * 1024 + k0 + c * 8, (m < M) ? 16 : 0);
        } else {
            cpa16z(dst, Wh + (long long)(colTile + row) * 1024 + k0 + c * 8, 16);
        }
    }
}

// MODE 0: fp32 out[m*1024+n];  MODE 1: video qkv + rope;  MODE 2: action qkv
template <int MODE>
__device__ __forceinline__ void gemm_body(const unsigned short* Ah,
                                          int M, int rowTile,
                                          const unsigned short* Wh,
                                          int colTile, const float* bias,
                                          float* __restrict__ outf,
                                          unsigned short* __restrict__ oh, int rk)
{
    extern __shared__ char dsmem[];
    const uint32_t sbase = smem_u32(dsmem);
    const int tid = threadIdx.x;
    const int lane = tid & 31, wid = tid >> 5;
    const int warp_m = wid >> 2, warp_n = wid & 3;

    float acc[2][4][4];
#pragma unroll
    for (int a = 0; a < 2; a++)
#pragma unroll
        for (int b = 0; b < 4; b++)
#pragma unroll
            for (int c = 0; c < 4; c++) acc[a][b][c] = 0.f;

    int rA[2], rW[2];
#pragma unroll
    for (int mt = 0; mt < 2; mt++) rA[mt] = warp_m * 32 + mt * 16 + (lane & 15);
#pragma unroll
    for (int nt2 = 0; nt2 < 2; nt2++) rW[nt2] = warp_n * 32 + nt2 * 16 + (lane & 15);
    const int khalf = lane >> 4;

    gstage(Ah, M, rowTile, Wh, colTile, 0, sbase, tid);
    cp_commit();

    for (int c = 0; c < 16; c++) {
        if (c + 1 < 16) {
            gstage(Ah, M, rowTile, Wh, colTile, (c + 1) * 64,
                   sbase + ((c + 1) & 1) * GT_BUF, tid);
            cp_commit();
            asm volatile("cp.async.wait_group 1;" ::: "memory");
        } else {
            asm volatile("cp.async.wait_group 0;" ::: "memory");
        }
        __syncthreads();

        const uint32_t bufb = sbase + (c & 1) * GT_BUF;
        const uint32_t sAh = bufb;
        const uint32_t sWh = bufb + GT_TILE;

#pragma unroll
        for (int kq = 0; kq < 4; kq++) {
            const int kp = 2 * kq + khalf;
            uint32_t ah[2][4], wh[2][4];
#pragma unroll
            for (int mt = 0; mt < 2; mt++) {
                const uint32_t off = (rA[mt] << 7) + ((kp ^ (rA[mt] & 7)) << 4);
                ldm4(ah[mt], sAh + off);
            }
#pragma unroll
            for (int nt2 = 0; nt2 < 2; nt2++) {
                const uint32_t off = (rW[nt2] << 7) + ((kp ^ (rW[nt2] & 7)) << 4);
                ldm4(wh[nt2], sWh + off);
            }
#pragma unroll
            for (int mt = 0; mt < 2; mt++) {
#pragma unroll
                for (int nt = 0; nt < 4; nt++) {
                    const uint32_t* whf = wh[nt >> 1];
                    mma16816(acc[mt][nt], ah[mt], whf[nt & 1], whf[(nt & 1) + 2]);
                }
            }
        }
        __syncthreads();
    }

    const int g = lane >> 2, tg = lane & 3;
#pragma unroll
    for (int mt = 0; mt < 2; mt++) {
#pragma unroll
        for (int nt = 0; nt < 4; nt++) {
            const int n0 = colTile + warp_n * 32 + nt * 8 + tg * 2;
            const float2 bv = *(const float2*)(bias + n0);
#pragma unroll
            for (int hf = 0; hf < 2; hf++) {
                const int m = rowTile + warp_m * 32 + mt * 16 + g + hf * 8;
                if (m >= M) continue;
                float v0 = acc[mt][nt][hf * 2 + 0] + bv.x;
                float v1 = acc[mt][nt][hf * 2 + 1] + bv.y;
                if (MODE == 0) {
                    float2 o; o.x = v0; o.y = v1;
                    *(float2*)(outf + (long long)m * 1024 + n0) = o;
                } else {
                    int b_, nn;
                    if (MODE == 1) { b_ = m >> 11; nn = m & 2047; }
                    else           { b_ = m >> 4;  nn = NVID + (m & 15); }
                    const int hh = n0 >> 6, d = n0 & 63;
                    if (MODE == 1 && rk && d < 60) {
                        const int seg = d / 20, jj = (d - seg * 20) >> 1;
                        const int pos = (seg == 0) ? (nn >> 8)
                                      : (seg == 1) ? ((nn >> 4) & 15) : (nn & 15);
                        const float omega = ex2f(-(float)jj * 1.3287712379549449f);
                        float sn, cs;
                        sincosf((float)pos * omega, &sn, &cs);
                        const float x1 = v0 * cs - v1 * sn;
                        const float x2 = v1 * cs + v0 * sn;
                        v0 = x1; v1 = x2;
                    }
                    if (rk == 1) { v0 *= QSC; v1 *= QSC; }
                    const long long idx = (((long long)(b_ * HEADS + hh)) * NTOT + nn) * HD + d;
                    *(ushort2*)(oh + idx) = make_ushort2(h16(v0), h16(v1));
                }
            }
        }
    }
}

// grid (8, 33, 3): z = {q,k,v}; by<32 video rows; by==32 action rows
__global__ __launch_bounds__(512, 1)
void gemm_qkv_mma(const float* bq, const float* bk, const float* bv,
                  const float* bqa, const float* bka, const float* bva)
{
    const int z = blockIdx.z;
    const bool act = (blockIdx.y == 32);
    const unsigned short* Ah = g_bh + (act ? OFF_ACTION : OFF_VIDEO);
    const int M = act ? (BSZ * NACT) : (BSZ * NVID);
    const int rowTile = act ? 0 : blockIdx.y * 128;
    const int colTile = blockIdx.x * 128;
    const int widx = z + (act ? 3 : 0);
    const unsigned short* Wh = g_bh + OFF_W + widx * WSZ;
    const float* bias = act ? (z == 0 ? bqa : (z == 1 ? bka : bva))
                            : (z == 0 ? bq : (z == 1 ? bk : bv));
    unsigned short* oh;
    int rk;
    if (z == 0)      { oh = g_qh; rk = 1; }
    else if (z == 1) { oh = g_kh; rk = 2; }
    else             { oh = g_vh; rk = 0; }
    if (act) gemm_body<2>(Ah, M, rowTile, Wh, colTile, bias, nullptr, oh, rk);
    else     gemm_body<1>(Ah, M, rowTile, Wh, colTile, bias, nullptr, oh, rk);
}

// grid (8, 17, 2): z = batch; by<16 video rows; by==16 action rows
__global__ __launch_bounds__(512, 1)
void gemm_out_mma(const float* bp, const float* bpa, float* __restrict__ dout)
{
    const int z = blockIdx.z;
    const bool act = (blockIdx.y == 16);
    const long long aoff = OFF_CTX + (long long)z * NTOT * HIDDEN +
                           (act ? (long long)NVID * HIDDEN : 0);
    const unsigned short* Ah = g_bh + aoff;
    const int M = act ? NACT : NVID;
    const int rowTile = act ? 0 : blockIdx.y * 128;
    const int colTile = blockIdx.x * 128;
    const int widx = act ? 7 : 6;
    const unsigned short* Wh = g_bh + OFF_W + widx * WSZ;
    const float* bias = act ? bpa : bp;
    float* C = act ? (dout + (long long)BSZ * NVID * HIDDEN + (long long)z * NACT * HIDDEN)
                   : (dout + (long long)z * NVID * HIDDEN);
    gemm_body<0>(Ah, M, rowTile, Wh, colTile, bias, C, nullptr, 0);
}

// ================= flash attention: 64 q-rows, 4 warps, 4 CTAs/SM ==============
// Triple-buffered fused K+V tiles (16 KB each: K at +0, V at +8K).
// One wait_group + one __syncthreads per key tile; prefetch distance 2.
#define AT_QOFF 0
#define AT_BUF(i) (8192 + (i) * 16384)
#define AT_SMEM (8192 + 3 * 16384)    // 57344

__device__ __forceinline__ void stage_kv64(long long base, int kt, uint32_t bufb, int tid) {
#pragma unroll
    for (int i = 0; i < 8; i++) {
        const int arr = i >> 2;                  // 0 = K, 1 = V
        const int t = ((i & 3) << 7) + tid;      // 0..511
        const int row = t >> 3, c = t & 7;
        const int key = kt * 64 + row;
        const uint32_t dst = bufb + arr * 8192 + (row << 7) + ((c ^ (row & 7)) << 4);
        const unsigned short* s = (arr == 0 ? g_kh : g_vh) +
            base + (long long)(key < NTOT ? key : 0) * HD + c * 8;
        cpa16z(dst, s, (key < NTOT) ? 16 : 0);
    }
}

__global__ __launch_bounds__(128, 4)
void attn_mma()
{
    extern __shared__ char dsm[];
    const uint32_t sb = smem_u32(dsm);
    const int tid = threadIdx.x, lane = tid & 31, w = tid >> 5;
    const int qt = blockIdx.x, bh = blockIdx.y;
    const int b = bh >> 4, h = bh & 15;
    const long long base = (long long)bh * NTOT * HD;
    const int g = lane >> 2, tg = lane & 3;
    const int khalf = lane >> 4, l15 = lane & 15;

    // prologue: G0 = {Q, KV0}, G1 = {KV1}
#pragma unroll
    for (int i = 0; i < 4; i++) {
        const int t = (i << 7) + tid;
        const int row = t >> 3, c = t & 7;
        const int n = qt * 64 + row;
        const uint32_t dst = sb + AT_QOFF + (row << 7) + ((c ^ (row & 7)) << 4);
        const unsigned short* src = g_qh + base + (long long)(n < NTOT ? n : 0) * HD + c * 8;
        cpa16z(dst, src, (n < NTOT) ? 16 : 0);
    }
    stage_kv64(base, 0, sb + AT_BUF(0), tid);
    cp_commit();
    stage_kv64(base, 1, sb + AT_BUF(1), tid);
    cp_commit();

    float oacc[8][4];
#pragma unroll
    for (int i = 0; i < 8; i++)
#pragma unroll
        for (int j = 0; j < 4; j++) oacc[i][j] = 0.f;
    float m0 = -1e30f, m1 = -1e30f, l0 = 0.f, l1 = 0.f;
    uint32_t qfh[4][4];

    const int NKT = 33;   // 33 * 64 = 2112 >= 2064
    int bi = 0;           // kt % 3
    for (int kt = 0; kt < NKT; kt++) {
        // ensure KV(kt) landed (KV(kt+1) may still be in flight)
        asm volatile("cp.async.wait_group 1;" ::: "memory");
        __syncthreads();

        if (kt == 0) {   // Q fragments (once)
            const int row = w * 16 + l15;
#pragma unroll
            for (int kq = 0; kq < 4; kq++) {
                const int kp = 2 * kq + khalf;
                const uint32_t off = (row << 7) + ((kp ^ (row & 7)) << 4);
                ldm4(qfh[kq], sb + AT_QOFF + off);
            }
        }

        // prefetch KV(kt+2) into the buffer consumed at iteration kt-1
        if (kt + 2 < NKT) {
            int nb = bi + 2; if (nb >= 3) nb -= 3;
            stage_kv64(base, kt + 2, sb + AT_BUF(nb), tid);
        }
        cp_commit();   // always commit to keep group accounting aligned

        const uint32_t sKh = sb + AT_BUF(bi);
        const uint32_t sVh = sKh + 8192;

        float sacc[8][4];
#pragma unroll
        for (int i = 0; i < 8; i++)
#pragma unroll
            for (int j = 0; j < 4; j++) sacc[i][j] = 0.f;

        // S = Q*K, 64 keys
#pragma unroll
        for (int kq = 0; kq < 4; kq++) {
            const int kp = 2 * kq + khalf;
#pragma unroll
            for (int ng = 0; ng < 4; ng++) {
                const int row = ng * 16 + l15;
                const uint32_t off = (row << 7) + ((kp ^ (row & 7)) << 4);
                uint32_t kh4[4];
                ldm4(kh4, sKh + off);
                mma16816(sacc[2 * ng + 0], qfh[kq], kh4[0], kh4[2]);
                mma16816(sacc[2 * ng + 1], qfh[kq], kh4[1], kh4[3]);
            }
        }

        // mask + online softmax (base-2)
        const int kvalid = NTOT - kt * 64;
        if (kvalid < 64) {
#pragma unroll
            for (int nt = 0; nt < 8; nt++) {
                const int c0 = nt * 8 + 2 * tg;
                if (c0 >= kvalid)     { sacc[nt][0] = -1e30f; sacc[nt][2] = -1e30f; }
                if (c0 + 1 >= kvalid) { sacc[nt][1] = -1e30f; sacc[nt][3] = -1e30f; }
            }
        }
        float mx0 = -1e30f, mx1 = -1e30f;
#pragma unroll
        for (int nt = 0; nt < 8; nt++) {
            mx0 = fmaxf(mx0, fmaxf(sacc[nt][0], sacc[nt][1]));
            mx1 = fmaxf(mx1, fmaxf(sacc[nt][2], sacc[nt][3]));
        }
        mx0 = fmaxf(mx0, __shfl_xor_sync(0xffffffffu, mx0, 1));
        mx0 = fmaxf(mx0, __shfl_xor_sync(0xffffffffu, mx0, 2));
        mx1 = fmaxf(mx1, __shfl_xor_sync(0xffffffffu, mx1, 1));
        mx1 = fmaxf(mx1, __shfl_xor_sync(0xffffffffu, mx1, 2));
        const float mn0 = fmaxf(m0, mx0), mn1 = fmaxf(m1, mx1);
        const float cr0 = ex2f(m0 - mn0), cr1 = ex2f(m1 - mn1);
        m0 = mn0; m1 = mn1;
        float s0 = 0.f, s1 = 0.f;
#pragma unroll
        for (int nt = 0; nt < 8; nt++) {
            sacc[nt][0] = ex2f(sacc[nt][0] - mn0);
            sacc[nt][1] = ex2f(sacc[nt][1] - mn0);
            sacc[nt][2] = ex2f(sacc[nt][2] - mn1);
            sacc[nt][3] = ex2f(sacc[nt][3] - mn1);
            s0 += sacc[nt][0] + sacc[nt][1];
            s1 += sacc[nt][2] + sacc[nt][3];
        }
        s0 += __shfl_xor_sync(0xffffffffu, s0, 1);
        s0 += __shfl_xor_sync(0xffffffffu, s0, 2);
        s1 += __shfl_xor_sync(0xffffffffu, s1, 1);
        s1 += __shfl_xor_sync(0xffffffffu, s1, 2);
        l0 = l0 * cr0 + s0; l1 = l1 * cr1 + s1;
#pragma unroll
        for (int nt = 0; nt < 8; nt++) {
            oacc[nt][0] *= cr0; oacc[nt][1] *= cr0;
            oacc[nt][2] *= cr1; oacc[nt][3] *= cr1;
        }

        // O += P*V (V already resident in the same buffer)
#pragma unroll
        for (int kc = 0; kc < 4; kc++) {
            uint32_t pah[4];
            const float* t0 = sacc[2 * kc];
            const float* t1 = sacc[2 * kc + 1];
            pah[0] = pkh(t0[0], t0[1]);
            pah[1] = pkh(t0[2], t0[3]);
            pah[2] = pkh(t1[0], t1[1]);
            pah[3] = pkh(t1[2], t1[3]);
            const int row = kc * 16 + l15;
#pragma unroll
            for (int ng = 0; ng < 4; ng++) {
                const int cc = 2 * ng + khalf;
                const uint32_t off = (row << 7) + ((cc ^ (row & 7)) << 4);
                uint32_t vh4[4];
                ldm4t(vh4, sVh + off);
                mma16816(oacc[2 * ng + 0], pah, vh4[0], vh4[1]);
                mma16816(oacc[2 * ng + 1], pah, vh4[2], vh4[3]);
            }
        }

        if (++bi == 3) bi = 0;
    }

    // normalize + write ctx as fp16 (out-proj A side)
    const float iv0 = 1.f / l0, iv1 = 1.f / l1;
    const int n0 = qt * 64 + w * 16 + g;
    const int n1 = n0 + 8;
#pragma unroll
    for (int nt = 0; nt < 8; nt++) {
        const int d = nt * 8 + 2 * tg;
        if (n0 < NTOT) {
            const long long idx = OFF_CTX + ((long long)(b * NTOT + n0)) * HIDDEN + h * HD + d;
            *(ushort2*)(g_bh + idx) = make_ushort2(h16(oacc[nt][0] * iv0),
                                                   h16(oacc[nt][1] * iv0));
        }
        if (n1 < NTOT) {
            const long long idx = OFF_CTX + ((long long)(b * NTOT + n1)) * HIDDEN + h * HD + d;
            *(ushort2*)(g_bh + idx) = make_ushort2(h16(oacc[nt][2] * iv1),
                                                   h16(oacc[nt][3] * iv1));
        }
    }
}

// ---------------- host launcher ----------------
extern "C" void kernel_launch(void* const* d_in, const int* in_sizes, int n_in,
                              void* d_out, int out_size)
{
    (void)out_size;
    const float* video = nullptr;
    const float* action = nullptr;
    const float* wb[16];
    int wi = 0;
    for (int i = 0; i < n_in; i++) {
        const int sz = in_sizes[i];
        if (sz == BSZ * NVID * HIDDEN)       video  = (const float*)d_in[i];
        else if (sz == BSZ * NACT * HIDDEN)  action = (const float*)d_in[i];
        else if (wi < 16)                    wb[wi++] = (const float*)d_in[i];
    }
    float* out = (float*)d_out;

    cudaFuncSetAttribute(gemm_qkv_mma, cudaFuncAttributeMaxDynamicSharedMemorySize, GT_SMEM);
    cudaFuncSetAttribute(gemm_out_mma, cudaFuncAttributeMaxDynamicSharedMemorySize, GT_SMEM);
    cudaFuncSetAttribute(attn_mma, cudaFuncAttributeMaxDynamicSharedMemorySize, AT_SMEM);

    // convert inputs + weights to fp16
    cvt_all<<<dim3(512, 10), 256>>>(video, action, wb[0], wb[2], wb[4], wb[6],
                                    wb[8], wb[10], wb[12], wb[14]);

    // QKV projections (rope + scale fused in epilogue)
    gemm_qkv_mma<<<dim3(8, 33, 3), 512, GT_SMEM>>>(wb[1], wb[3], wb[5],
                                                   wb[7], wb[9], wb[11]);

    // attention: 64-q-row CTAs, 4 CTAs/SM, fused KV triple buffer
    attn_mma<<<dim3(33, 32), 128, AT_SMEM>>>();

    // output projection
    gemm_out_mma<<<dim3(8, 17, 2), 512, GT_SMEM>>>(wb[13], wb[15], out);
}